// round 1
// baseline (speedup 1.0000x reference)
#include <cuda_runtime.h>
#include <math.h>
#include <stdint.h>

// Problem constants
#define BB   2
#define HH   16
#define SS   2048
#define DDIM 1024
#define DH   64
#define PFX  32
#define LKV  2080          // PFX + SS
#define BIAS_STRIDE 4160   // >= 4127, padded
#define BIAS_OFF 2079      // rel + BIAS_OFF in [0, 4126]

// ---------------- scratch (static device globals; no allocation) ----------------
__device__ float g_qT[(size_t)BB * HH * DH * SS];    // [b][h][d][s]
__device__ float g_kT[(size_t)BB * HH * DH * LKV];   // [b][h][d][key]
__device__ float g_v [(size_t)BB * HH * LKV * DH];   // [b][h][key][d]
__device__ float g_attn[(size_t)BB * SS * DDIM];     // [b][s][h*64+d]
__device__ float g_bias[HH * BIAS_STRIDE];           // [h][rel+2079]

// ---------------- bias table init (T5 relative position bucketing) ----------------
__global__ void bias_init_kernel(const float* __restrict__ rel_table)
{
    int idx = blockIdx.x * blockDim.x + threadIdx.x;
    const int total = HH * 4127;
    if (idx >= total) return;
    int h   = idx / 4127;
    int r   = idx - h * 4127;       // 0..4126
    int rel = r - BIAS_OFF;         // -2079..2047

    int ret = (rel > 0) ? 16 : 0;   // num_buckets//2
    int n   = rel < 0 ? -rel : rel;
    int bkt;
    if (n < 8) {
        bkt = n;
    } else {
        float nf = (float)n;
        // matches: log(nf/8) / log(16) * 8, truncated to int32
        int vl = 8 + (int)(logf(nf * 0.125f) / 2.772588722239781f * 8.0f);
        bkt = vl < 15 ? vl : 15;
    }
    bkt += ret;
    g_bias[h * BIAS_STRIDE + r] = rel_table[bkt * HH + h];
}

// ---------------- prefix K/V copy (with K transpose) ----------------
__global__ void prefix_copy_kernel(const float* __restrict__ pk,
                                   const float* __restrict__ pv)
{
    int idx = blockIdx.x * blockDim.x + threadIdx.x;
    const int total = BB * HH * PFX * DH;   // 65536
    if (idx >= total) return;
    int d  = idx & 63;
    int p  = (idx >> 6) & 31;
    int bh = idx >> 11;
    g_kT[((size_t)bh * DH + d) * LKV + p]  = pk[idx];
    g_v [((size_t)bh * LKV + p) * DH + d]  = pv[idx];
}

// ---------------- shared 128x128x8 SGEMM core (8x8 register tiles) ----------------
__device__ __forceinline__ void gemm_core(const float* __restrict__ A,
                                          const float* __restrict__ W,
                                          int mblock, int nblock,
                                          float (*As)[128], float (*Bs)[128],
                                          float acc[8][8])
{
    const int t    = threadIdx.x;
    const int tx   = t & 15;
    const int ty   = t >> 4;
    const int arow = t >> 1;
    const int acol = (t & 1) << 2;
    const int brow = t >> 5;
    const int bcol = (t & 31) << 2;

    const float* aptr = A + (size_t)(mblock + arow) * DDIM + acol;
    const float* wptr = W + (size_t)brow * DDIM + nblock + bcol;

    float4 av = *(const float4*)(aptr);
    float4 wv = *(const float4*)(wptr);

    #pragma unroll 1
    for (int k0 = 0; k0 < DDIM; k0 += 8) {
        __syncthreads();
        As[acol + 0][arow] = av.x;
        As[acol + 1][arow] = av.y;
        As[acol + 2][arow] = av.z;
        As[acol + 3][arow] = av.w;
        *(float4*)&Bs[brow][bcol] = wv;
        __syncthreads();
        if (k0 + 8 < DDIM) {
            av = *(const float4*)(aptr + k0 + 8);
            wv = *(const float4*)(wptr + (size_t)(k0 + 8) * DDIM);
        }
        #pragma unroll
        for (int kk = 0; kk < 8; kk++) {
            float a[8], b[8];
            *(float4*)(a)     = *(float4*)&As[kk][ty * 4];
            *(float4*)(a + 4) = *(float4*)&As[kk][64 + ty * 4];
            *(float4*)(b)     = *(float4*)&Bs[kk][tx * 4];
            *(float4*)(b + 4) = *(float4*)&Bs[kk][64 + tx * 4];
            #pragma unroll
            for (int i = 0; i < 8; i++)
                #pragma unroll
                for (int j = 0; j < 8; j++)
                    acc[i][j] += a[i] * b[j];
        }
    }
}

// ---------------- QKV projection GEMM (z=0:Q, 1:K, 2:V) ----------------
__global__ __launch_bounds__(256) void gemm_qkv_kernel(const float* __restrict__ A,
                                                       const float* __restrict__ Wq,
                                                       const float* __restrict__ Wk,
                                                       const float* __restrict__ Wv)
{
    __shared__ float As[8][128];
    __shared__ float Bs[8][128];
    const int z = blockIdx.z;
    const float* W = (z == 0) ? Wq : (z == 1) ? Wk : Wv;

    float acc[8][8];
    #pragma unroll
    for (int i = 0; i < 8; i++)
        #pragma unroll
        for (int j = 0; j < 8; j++) acc[i][j] = 0.f;

    const int mblock = blockIdx.y * 128;
    const int nblock = blockIdx.x * 128;
    gemm_core(A, W, mblock, nblock, As, Bs, acc);

    const int t  = threadIdx.x;
    const int tx = t & 15;
    const int ty = t >> 4;
    const int b0    = mblock >> 11;      // batch (uniform within block)
    const int sbase = mblock & 2047;

    if (z < 2) {
        // transposed layouts: g_qT [bh][d][s] / g_kT [bh][d][key=32+s]
        const size_t ld   = (z == 0) ? (size_t)SS : (size_t)LKV;
        float* buf        = (z == 0) ? g_qT : g_kT;
        const int off     = (z == 0) ? 0 : PFX;
        #pragma unroll
        for (int j = 0; j < 8; j++) {
            int c = nblock + ((j < 4) ? (tx * 4 + j) : (64 + tx * 4 + j - 4));
            int h = c >> 6, d = c & 63;
            float* base = buf + ((size_t)(b0 * HH + h) * DH + d) * ld + off + sbase;
            float4 v0 = make_float4(acc[0][j], acc[1][j], acc[2][j], acc[3][j]);
            float4 v1 = make_float4(acc[4][j], acc[5][j], acc[6][j], acc[7][j]);
            *(float4*)(base + ty * 4)      = v0;
            *(float4*)(base + 64 + ty * 4) = v1;
        }
    } else {
        // natural V layout: g_v [bh][key=32+s][d]
        const int c0 = nblock + tx * 4;
        const int c1 = c0 + 64;
        const size_t base0 = ((size_t)(b0 * HH + (c0 >> 6)) * LKV + PFX) * DH + (c0 & 63);
        const size_t base1 = ((size_t)(b0 * HH + (c1 >> 6)) * LKV + PFX) * DH + (c1 & 63);
        #pragma unroll
        for (int i = 0; i < 8; i++) {
            int s = sbase + ((i < 4) ? (ty * 4 + i) : (64 + ty * 4 + i - 4));
            float4 v0 = make_float4(acc[i][0], acc[i][1], acc[i][2], acc[i][3]);
            float4 v1 = make_float4(acc[i][4], acc[i][5], acc[i][6], acc[i][7]);
            *(float4*)(g_v + base0 + (size_t)s * DH) = v0;
            *(float4*)(g_v + base1 + (size_t)s * DH) = v1;
        }
    }
}

// ---------------- output projection GEMM (plain row-major C) ----------------
__global__ __launch_bounds__(256) void gemm_o_kernel(const float* __restrict__ Wo,
                                                     float* __restrict__ Cout)
{
    __shared__ float As[8][128];
    __shared__ float Bs[8][128];
    float acc[8][8];
    #pragma unroll
    for (int i = 0; i < 8; i++)
        #pragma unroll
        for (int j = 0; j < 8; j++) acc[i][j] = 0.f;

    const int mblock = blockIdx.y * 128;
    const int nblock = blockIdx.x * 128;
    gemm_core(g_attn, Wo, mblock, nblock, As, Bs, acc);

    const int t  = threadIdx.x;
    const int tx = t & 15;
    const int ty = t >> 4;
    #pragma unroll
    for (int i = 0; i < 8; i++) {
        size_t r = mblock + ((i < 4) ? (ty * 4 + i) : (64 + ty * 4 + i - 4));
        float4 v0 = make_float4(acc[i][0], acc[i][1], acc[i][2], acc[i][3]);
        float4 v1 = make_float4(acc[i][4], acc[i][5], acc[i][6], acc[i][7]);
        *(float4*)(Cout + r * DDIM + nblock + tx * 4)      = v0;
        *(float4*)(Cout + r * DDIM + nblock + 64 + tx * 4) = v1;
    }
}

// ---------------- flash-style attention ----------------
// grid: (SS/64, HH, BB), block 256.
// smem: Qt[d][q] 16KB + KB[.][.] 16KB (K tile during scores, P tile during PV) + Vt[key][d] 16KB = 48KB
__global__ __launch_bounds__(256) void attn_kernel(const float* __restrict__ mask)
{
    __shared__ float Qt[64][64];   // [d][q]
    __shared__ float KB[64][64];   // scores phase: [d][key]; PV phase: P as [q][key]
    __shared__ float Vt[64][64];   // [key][d]

    const int t  = threadIdx.x;
    const int tx = t & 15;         // key/d-col group
    const int ty = t >> 4;         // query group
    const int h  = blockIdx.y;
    const int b  = blockIdx.z;
    const int bh = b * HH + h;
    const int qbase = blockIdx.x * 64;

    // load Q tile (transposed global -> direct smem)
    {
        const int d  = t >> 2;
        const int c0 = (t & 3) * 4;
        const float* src = g_qT + ((size_t)bh * DH + d) * SS + qbase;
        #pragma unroll
        for (int i = 0; i < 4; i++)
            *(float4*)&Qt[d][c0 + 16 * i] = *(const float4*)(src + c0 + 16 * i);
    }

    float O[4][4];
    #pragma unroll
    for (int v = 0; v < 4; v++)
        #pragma unroll
        for (int u = 0; u < 4; u++) O[v][u] = 0.f;
    float m[4], l[4];
    #pragma unroll
    for (int v = 0; v < 4; v++) { m[v] = -INFINITY; l[v] = 0.f; }

    const float* maskb = mask + b * SS;
    const float* biash = g_bias + h * BIAS_STRIDE;

    const int NTILES = (LKV + 63) / 64;   // 33
    for (int kt = 0; kt < NTILES; kt++) {
        const int kbase = kt * 64;

        // prefetch K (transposed layout) and V tiles to registers
        float4 kreg[4], vreg[4];
        {
            const int d  = t >> 2;
            const int c0 = (t & 3) * 4;
            const float* ks = g_kT + ((size_t)bh * DH + d) * LKV + kbase;
            #pragma unroll
            for (int i = 0; i < 4; i++) {
                int col = c0 + 16 * i;
                kreg[i] = (kbase + col < LKV) ? *(const float4*)(ks + col)
                                              : make_float4(0.f, 0.f, 0.f, 0.f);
            }
            const int key = t >> 2;
            const float* vs = g_v + ((size_t)bh * LKV + kbase + key) * DH;
            const bool vvalid = (kbase + key) < LKV;
            #pragma unroll
            for (int i = 0; i < 4; i++) {
                int col = c0 + 16 * i;
                vreg[i] = vvalid ? *(const float4*)(vs + col)
                                 : make_float4(0.f, 0.f, 0.f, 0.f);
            }
        }
        __syncthreads();   // previous PV done reading KB(P)/Vt
        {
            const int d  = t >> 2;
            const int c0 = (t & 3) * 4;
            #pragma unroll
            for (int i = 0; i < 4; i++) *(float4*)&KB[d][c0 + 16 * i] = kreg[i];
            const int key = t >> 2;
            #pragma unroll
            for (int i = 0; i < 4; i++) *(float4*)&Vt[key][c0 + 16 * i] = vreg[i];
        }
        __syncthreads();

        // scores: s[v][u] = q(ty*4+v) . k(tx*4+u)
        float s[4][4];
        #pragma unroll
        for (int v = 0; v < 4; v++)
            #pragma unroll
            for (int u = 0; u < 4; u++) s[v][u] = 0.f;
        #pragma unroll 8
        for (int d = 0; d < 64; d++) {
            float4 q4 = *(float4*)&Qt[d][ty * 4];
            float4 k4 = *(float4*)&KB[d][tx * 4];
            float qv[4] = {q4.x, q4.y, q4.z, q4.w};
            float kv[4] = {k4.x, k4.y, k4.z, k4.w};
            #pragma unroll
            for (int v = 0; v < 4; v++)
                #pragma unroll
                for (int u = 0; u < 4; u++) s[v][u] += qv[v] * kv[u];
        }

        // bias + mask (or -inf for out-of-range keys)
        #pragma unroll
        for (int u = 0; u < 4; u++) {
            const int j = kbase + tx * 4 + u;
            if (j < LKV) {
                const float mval = (j >= PFX) ? maskb[j - PFX] : 0.f;
                #pragma unroll
                for (int v = 0; v < 4; v++) {
                    const int qg = qbase + ty * 4 + v;
                    s[v][u] += biash[j - qg - PFX + BIAS_OFF] + mval;
                }
            } else {
                #pragma unroll
                for (int v = 0; v < 4; v++) s[v][u] = -INFINITY;
            }
        }

        // online softmax (reduce across the 16 tx-lanes of each half-warp)
        float alpha[4];
        #pragma unroll
        for (int v = 0; v < 4; v++) {
            float tm = fmaxf(fmaxf(s[v][0], s[v][1]), fmaxf(s[v][2], s[v][3]));
            #pragma unroll
            for (int off = 8; off >= 1; off >>= 1)
                tm = fmaxf(tm, __shfl_xor_sync(0xffffffffu, tm, off));
            const float mn = fmaxf(m[v], tm);
            alpha[v] = __expf(m[v] - mn);
            m[v] = mn;
            float rs = 0.f;
            #pragma unroll
            for (int u = 0; u < 4; u++) {
                s[v][u] = __expf(s[v][u] - mn);
                rs += s[v][u];
            }
            #pragma unroll
            for (int off = 8; off >= 1; off >>= 1)
                rs += __shfl_xor_sync(0xffffffffu, rs, off);
            l[v] = l[v] * alpha[v] + rs;
        }
        #pragma unroll
        for (int v = 0; v < 4; v++)
            #pragma unroll
            for (int u = 0; u < 4; u++) O[v][u] *= alpha[v];

        __syncthreads();   // everyone done reading K from KB
        #pragma unroll
        for (int v = 0; v < 4; v++)
            *(float4*)&KB[ty * 4 + v][tx * 4] = make_float4(s[v][0], s[v][1], s[v][2], s[v][3]);
        __syncthreads();

        // PV: O[v][u] += sum_j P[q][j] * V[j][d]
        #pragma unroll 4
        for (int j = 0; j < 64; j++) {
            float4 v4 = *(float4*)&Vt[j][tx * 4];
            float vv[4] = {v4.x, v4.y, v4.z, v4.w};
            float pv[4];
            #pragma unroll
            for (int v = 0; v < 4; v++) pv[v] = KB[ty * 4 + v][j];
            #pragma unroll
            for (int v = 0; v < 4; v++)
                #pragma unroll
                for (int u = 0; u < 4; u++) O[v][u] += pv[v] * vv[u];
        }
    }

    // epilogue: normalize and write [b][s][h*64+d]
    #pragma unroll
    for (int v = 0; v < 4; v++) {
        const float inv = 1.0f / l[v];
        float4 o = make_float4(O[v][0] * inv, O[v][1] * inv, O[v][2] * inv, O[v][3] * inv);
        *(float4*)(g_attn + ((size_t)b * SS + qbase + ty * 4 + v) * DDIM + h * DH + tx * 4) = o;
    }
}

// ---------------- launch ----------------
extern "C" void kernel_launch(void* const* d_in, const int* in_sizes, int n_in,
                              void* d_out, int out_size)
{
    const float* hidden = (const float*)d_in[0];
    const float* mask   = (const float*)d_in[1];
    const float* pk     = (const float*)d_in[2];
    const float* pv     = (const float*)d_in[3];
    const float* Wq     = (const float*)d_in[4];
    const float* Wk     = (const float*)d_in[5];
    const float* Wv     = (const float*)d_in[6];
    const float* Wo     = (const float*)d_in[7];
    const float* rel    = (const float*)d_in[8];
    float* out = (float*)d_out;

    bias_init_kernel<<<(HH * 4127 + 255) / 256, 256>>>(rel);
    prefix_copy_kernel<<<(BB * HH * PFX * DH + 255) / 256, 256>>>(pk, pv);
    gemm_qkv_kernel<<<dim3(DDIM / 128, (BB * SS) / 128, 3), 256>>>(hidden, Wq, Wk, Wv);
    attn_kernel<<<dim3(SS / 64, HH, BB), 256>>>(mask);
    gemm_o_kernel<<<dim3(DDIM / 128, (BB * SS) / 128), 256>>>(Wo, out);
}

// round 3
// speedup vs baseline: 1.2445x; 1.2445x over previous
#include <cuda_runtime.h>
#include <cuda_bf16.h>
#include <math.h>
#include <stdint.h>

// Problem constants
#define BB   2
#define HH   16
#define SS   2048
#define DDIM 1024
#define DH   64
#define PFX  32
#define LKV  2080          // PFX + SS
#define K3   3072          // 3x split-concatenated K
#define BIAS_STRIDE 4160
#define BIAS_OFF 2079

// ---------------- scratch (static device globals; no allocation) ----------------
__device__ float g_qT[(size_t)BB * HH * DH * SS];    // [b][h][d][s]
__device__ float g_kT[(size_t)BB * HH * DH * LKV];   // [b][h][d][key]
__device__ float g_v [(size_t)BB * HH * LKV * DH];   // [b][h][key][d]
__device__ float g_attn[(size_t)BB * SS * DDIM];     // [b][s][h*64+d]
__device__ float g_bias[HH * BIAS_STRIDE];           // [h][rel+2079]
__device__ __nv_bfloat16 g_a3[(size_t)BB * SS * K3]; // hidden split [m][k3]
__device__ __nv_bfloat16 g_w3[(size_t)4 * DDIM * K3];// Wq,Wk,Wv,Wo split+transposed [n][k3]
__device__ __nv_bfloat16 g_o3[(size_t)BB * SS * K3]; // attn-out split [m][k3]

// ======================= PTX helpers (sm_80-class only; NO "a" features) =======================
__device__ __forceinline__ uint32_t smem_u32(const void* p) {
    uint32_t a;
    asm("{ .reg .u64 t; cvta.to.shared.u64 t, %1; cvt.u32.u64 %0, t; }" : "=r"(a) : "l"(p));
    return a;
}
__device__ __forceinline__ void cpa16(uint32_t dst, const void* src) {
    asm volatile("cp.async.cg.shared.global [%0], [%1], 16;" :: "r"(dst), "l"(src));
}
__device__ __forceinline__ void ldsm_x4(uint32_t* r, uint32_t addr) {
    asm volatile("ldmatrix.sync.aligned.m8n8.x4.shared.b16 {%0,%1,%2,%3}, [%4];"
                 : "=r"(r[0]), "=r"(r[1]), "=r"(r[2]), "=r"(r[3]) : "r"(addr));
}
__device__ __forceinline__ void mma16816(float* d, const uint32_t* a, const uint32_t* b) {
    asm volatile("mma.sync.aligned.m16n8k16.row.col.f32.bf16.bf16.f32 "
                 "{%0,%1,%2,%3}, {%4,%5,%6,%7}, {%8,%9}, {%0,%1,%2,%3};"
                 : "+f"(d[0]), "+f"(d[1]), "+f"(d[2]), "+f"(d[3])
                 : "r"(a[0]), "r"(a[1]), "r"(a[2]), "r"(a[3]), "r"(b[0]), "r"(b[1]));
}
// swizzled smem element address: rows of 64B (32 bf16), quad = 16B unit
__device__ __forceinline__ uint32_t sw_addr(uint32_t base, int r, int k) {
    int quad = k >> 3;
    int sw   = quad ^ ((r >> 1) & 3);
    return base + r * 64 + sw * 16 + (k & 7) * 2;
}

// ---------------- bias table init ----------------
__global__ void bias_init_kernel(const float* __restrict__ rel_table)
{
    int idx = blockIdx.x * blockDim.x + threadIdx.x;
    const int total = HH * 4127;
    if (idx >= total) return;
    int h   = idx / 4127;
    int r   = idx - h * 4127;
    int rel = r - BIAS_OFF;

    int ret = (rel > 0) ? 16 : 0;
    int n   = rel < 0 ? -rel : rel;
    int bkt;
    if (n < 8) {
        bkt = n;
    } else {
        float nf = (float)n;
        int vl = 8 + (int)(logf(nf * 0.125f) / 2.772588722239781f * 8.0f);
        bkt = vl < 15 ? vl : 15;
    }
    bkt += ret;
    g_bias[h * BIAS_STRIDE + r] = rel_table[bkt * HH + h];
}

// ---------------- prefix K/V copy ----------------
__global__ void prefix_copy_kernel(const float* __restrict__ pk,
                                   const float* __restrict__ pv)
{
    int idx = blockIdx.x * blockDim.x + threadIdx.x;
    const int total = BB * HH * PFX * DH;
    if (idx >= total) return;
    int d  = idx & 63;
    int p  = (idx >> 6) & 31;
    int bh = idx >> 11;
    g_kT[((size_t)bh * DH + d) * LKV + p] = pk[idx];
    g_v [((size_t)bh * LKV + p) * DH + d] = pv[idx];
}

// ---------------- split kernels (bf16 hi/lo, 3x concat along K) ----------------
__device__ __forceinline__ void split_store_a(__nv_bfloat16* dst, size_t m, int k, float x)
{
    __nv_bfloat16 h = __float2bfloat16(x);
    __nv_bfloat16 l = __float2bfloat16(x - __bfloat162float(h));
    size_t b = m * K3 + k;
    dst[b]        = h;
    dst[b + 1024] = h;
    dst[b + 2048] = l;
}

__global__ void split_hidden_kernel(const float* __restrict__ src)
{
    int i = blockIdx.x * blockDim.x + threadIdx.x;
    const int n = BB * SS * DDIM;
    if (i >= n) return;
    split_store_a(g_a3, (size_t)(i >> 10), i & 1023, src[i]);
}

__global__ void split_o_kernel()
{
    int i = blockIdx.x * blockDim.x + threadIdx.x;
    const int n = BB * SS * DDIM;
    if (i >= n) return;
    split_store_a(g_o3, (size_t)(i >> 10), i & 1023, g_attn[i]);
}

// W [k][n] fp32 -> W3 [n][k3] bf16 = [hi | lo | hi] (transposed)
__global__ __launch_bounds__(256) void split_w_kernel(const float* __restrict__ Wq,
                                                      const float* __restrict__ Wk,
                                                      const float* __restrict__ Wv,
                                                      const float* __restrict__ Wo)
{
    __shared__ float tile[32][33];
    const int z = blockIdx.z;
    const float* W = (z == 0) ? Wq : (z == 1) ? Wk : (z == 2) ? Wv : Wo;
    __nv_bfloat16* dst = g_w3 + (size_t)z * DDIM * K3;

    const int n0 = blockIdx.x * 32, k0 = blockIdx.y * 32;
    const int tx = threadIdx.x & 31, ty0 = threadIdx.x >> 5;
    #pragma unroll
    for (int r = 0; r < 4; r++) {
        int ty = ty0 + r * 8;
        tile[ty][tx] = W[(size_t)(k0 + ty) * DDIM + n0 + tx];
    }
    __syncthreads();
    #pragma unroll
    for (int r = 0; r < 4; r++) {
        int ty = ty0 + r * 8;
        float x = tile[tx][ty];                    // = W[k0+tx][n0+ty]
        __nv_bfloat16 h = __float2bfloat16(x);
        __nv_bfloat16 l = __float2bfloat16(x - __bfloat162float(h));
        size_t b = (size_t)(n0 + ty) * K3 + (k0 + tx);
        dst[b]        = h;
        dst[b + 1024] = l;
        dst[b + 2048] = h;
    }
}

// ---------------- mma.sync bf16 GEMM: C[4096 x 1024] = A3 * W3^T ----------------
// CTA 128x128, K-chunk 32, 3 stages (48KB static smem), 8 warps (4m x 2n), warp tile 32x64
#define CHUNK 32
#define NSTG 3
#define STG_BYTES 16384      // A 8KB + B 8KB

__device__ __forceinline__ void gemm_load_chunk(uint32_t sb,
        const __nv_bfloat16* __restrict__ Ag, const __nv_bfloat16* __restrict__ Bg,
        int mblock, int nblock, int c)
{
    const int t = threadIdx.x;
    const int st = c % NSTG;
    uint32_t ab = sb + st * STG_BYTES;
    uint32_t bb = ab + 8192;
    #pragma unroll
    for (int i = 0; i < 2; i++) {
        int idx = t + i * 256;            // 0..511 -> 128 rows x 4 quads
        int r = idx >> 2, q = idx & 3;
        uint32_t soff = (uint32_t)(r * 64 + ((q ^ ((r >> 1) & 3)) << 4));
        const char* as = (const char*)(Ag + (size_t)(mblock + r) * K3 + c * CHUNK + q * 8);
        const char* bs = (const char*)(Bg + (size_t)(nblock + r) * K3 + c * CHUNK + q * 8);
        cpa16(ab + soff, as);
        cpa16(bb + soff, bs);
    }
    asm volatile("cp.async.commit_group;" ::: "memory");
}

__device__ __forceinline__ void gemm_mma_body(const __nv_bfloat16* __restrict__ Ag,
                                              const __nv_bfloat16* __restrict__ Bg,
                                              int mblock, int nblock, int flavor,
                                              float* __restrict__ outp)
{
    __shared__ __align__(128) char smbuf[NSTG * STG_BYTES];
    uint32_t sb = smem_u32(smbuf);
    const int t    = threadIdx.x;
    const int lane = t & 31;
    const int w    = t >> 5;
    const int wm   = w >> 1;     // 0..3
    const int wn   = w & 1;      // 0..1

    float acc[2][8][4];
    #pragma unroll
    for (int f = 0; f < 2; f++)
        #pragma unroll
        for (int p = 0; p < 8; p++)
            #pragma unroll
            for (int e = 0; e < 4; e++) acc[f][p][e] = 0.f;

    const int NCH = K3 / CHUNK;   // 96

    gemm_load_chunk(sb, Ag, Bg, mblock, nblock, 0);
    gemm_load_chunk(sb, Ag, Bg, mblock, nblock, 1);

    for (int c = 0; c < NCH; c++) {
        if (c < NCH - 1) asm volatile("cp.async.wait_group 1;" ::: "memory");
        else             asm volatile("cp.async.wait_group 0;" ::: "memory");
        __syncthreads();

        uint32_t ab = sb + (c % NSTG) * STG_BYTES;
        uint32_t bb = ab + 8192;

        #pragma unroll
        for (int ks = 0; ks < 2; ks++) {
            uint32_t afr[2][4];
            #pragma unroll
            for (int f = 0; f < 2; f++) {
                int r = wm * 32 + f * 16 + (lane & 15);
                int k = ks * 16 + (lane >> 4) * 8;
                ldsm_x4(afr[f], sw_addr(ab, r, k));
            }
            uint32_t bfr[8][2];
            #pragma unroll
            for (int p = 0; p < 4; p++) {
                int n = wn * 64 + p * 16 + ((lane >> 4) & 1) * 8 + (lane & 7);
                int k = ks * 16 + ((lane >> 3) & 1) * 8;
                uint32_t r4[4];
                ldsm_x4(r4, sw_addr(bb, n, k));
                bfr[p * 2][0]     = r4[0];
                bfr[p * 2][1]     = r4[1];
                bfr[p * 2 + 1][0] = r4[2];
                bfr[p * 2 + 1][1] = r4[3];
            }
            #pragma unroll
            for (int f = 0; f < 2; f++)
                #pragma unroll
                for (int p = 0; p < 8; p++)
                    mma16816(acc[f][p], afr[f], bfr[p]);
        }
        __syncthreads();
        if (c + 2 < NCH) gemm_load_chunk(sb, Ag, Bg, mblock, nblock, c + 2);
    }

    // epilogue: fragment (f,p,e): m = wm*32 + f*16 + (lane>>2) + (e>>1)*8
    //                              n = wn*64 + p*8 + (lane&3)*2 + (e&1)
    #pragma unroll
    for (int f = 0; f < 2; f++) {
        #pragma unroll
        for (int p = 0; p < 8; p++) {
            #pragma unroll
            for (int e = 0; e < 4; e++) {
                int m = mblock + wm * 32 + f * 16 + (lane >> 2) + ((e >> 1) << 3);
                int n = nblock + wn * 64 + p * 8 + ((lane & 3) << 1) + (e & 1);
                float val = acc[f][p][e];
                if (flavor == 0) {
                    int b0 = m >> 11, s = m & 2047, h = n >> 6, d = n & 63;
                    g_qT[((size_t)(b0 * HH + h) * DH + d) * SS + s] = val;
                } else if (flavor == 1) {
                    int b0 = m >> 11, s = m & 2047, h = n >> 6, d = n & 63;
                    g_kT[((size_t)(b0 * HH + h) * DH + d) * LKV + PFX + s] = val;
                } else if (flavor == 2) {
                    int b0 = m >> 11, s = m & 2047, h = n >> 6, d = n & 63;
                    g_v[((size_t)(b0 * HH + h) * LKV + PFX + s) * DH + d] = val;
                } else {
                    outp[(size_t)m * DDIM + n] = val;
                }
            }
        }
    }
}

__global__ __launch_bounds__(256) void gemm_qkv_mma()
{
    const int z = blockIdx.z;
    gemm_mma_body(g_a3, g_w3 + (size_t)z * DDIM * K3,
                  blockIdx.y * 128, blockIdx.x * 128, z, nullptr);
}

__global__ __launch_bounds__(256) void gemm_o_mma(float* __restrict__ out)
{
    gemm_mma_body(g_o3, g_w3 + (size_t)3 * DDIM * K3,
                  blockIdx.y * 128, blockIdx.x * 128, 3, out);
}

// ---------------- flash-style attention (fp32 SIMT, unchanged) ----------------
__global__ __launch_bounds__(256) void attn_kernel(const float* __restrict__ mask)
{
    __shared__ float Qt[64][64];
    __shared__ float KB[64][64];
    __shared__ float Vt[64][64];

    const int t  = threadIdx.x;
    const int tx = t & 15;
    const int ty = t >> 4;
    const int h  = blockIdx.y;
    const int b  = blockIdx.z;
    const int bh = b * HH + h;
    const int qbase = blockIdx.x * 64;

    {
        const int d  = t >> 2;
        const int c0 = (t & 3) * 4;
        const float* src = g_qT + ((size_t)bh * DH + d) * SS + qbase;
        #pragma unroll
        for (int i = 0; i < 4; i++)
            *(float4*)&Qt[d][c0 + 16 * i] = *(const float4*)(src + c0 + 16 * i);
    }

    float O[4][4];
    #pragma unroll
    for (int v = 0; v < 4; v++)
        #pragma unroll
        for (int u = 0; u < 4; u++) O[v][u] = 0.f;
    float m[4], l[4];
    #pragma unroll
    for (int v = 0; v < 4; v++) { m[v] = -INFINITY; l[v] = 0.f; }

    const float* maskb = mask + b * SS;
    const float* biash = g_bias + h * BIAS_STRIDE;

    const int NTILES = (LKV + 63) / 64;
    for (int kt = 0; kt < NTILES; kt++) {
        const int kbase = kt * 64;

        float4 kreg[4], vreg[4];
        {
            const int d  = t >> 2;
            const int c0 = (t & 3) * 4;
            const float* ks = g_kT + ((size_t)bh * DH + d) * LKV + kbase;
            #pragma unroll
            for (int i = 0; i < 4; i++) {
                int col = c0 + 16 * i;
                kreg[i] = (kbase + col < LKV) ? *(const float4*)(ks + col)
                                              : make_float4(0.f, 0.f, 0.f, 0.f);
            }
            const int key = t >> 2;
            const float* vs = g_v + ((size_t)bh * LKV + kbase + key) * DH;
            const bool vvalid = (kbase + key) < LKV;
            #pragma unroll
            for (int i = 0; i < 4; i++) {
                int col = c0 + 16 * i;
                vreg[i] = vvalid ? *(const float4*)(vs + col)
                                 : make_float4(0.f, 0.f, 0.f, 0.f);
            }
        }
        __syncthreads();
        {
            const int d  = t >> 2;
            const int c0 = (t & 3) * 4;
            #pragma unroll
            for (int i = 0; i < 4; i++) *(float4*)&KB[d][c0 + 16 * i] = kreg[i];
            const int key = t >> 2;
            #pragma unroll
            for (int i = 0; i < 4; i++) *(float4*)&Vt[key][c0 + 16 * i] = vreg[i];
        }
        __syncthreads();

        float s[4][4];
        #pragma unroll
        for (int v = 0; v < 4; v++)
            #pragma unroll
            for (int u = 0; u < 4; u++) s[v][u] = 0.f;
        #pragma unroll 8
        for (int d = 0; d < 64; d++) {
            float4 q4 = *(float4*)&Qt[d][ty * 4];
            float4 k4 = *(float4*)&KB[d][tx * 4];
            float qv[4] = {q4.x, q4.y, q4.z, q4.w};
            float kv[4] = {k4.x, k4.y, k4.z, k4.w};
            #pragma unroll
            for (int v = 0; v < 4; v++)
                #pragma unroll
                for (int u = 0; u < 4; u++) s[v][u] += qv[v] * kv[u];
        }

        #pragma unroll
        for (int u = 0; u < 4; u++) {
            const int j = kbase + tx * 4 + u;
            if (j < LKV) {
                const float mval = (j >= PFX) ? maskb[j - PFX] : 0.f;
                #pragma unroll
                for (int v = 0; v < 4; v++) {
                    const int qg = qbase + ty * 4 + v;
                    s[v][u] += biash[j - qg - PFX + BIAS_OFF] + mval;
                }
            } else {
                #pragma unroll
                for (int v = 0; v < 4; v++) s[v][u] = -INFINITY;
            }
        }

        float alpha[4];
        #pragma unroll
        for (int v = 0; v < 4; v++) {
            float tm = fmaxf(fmaxf(s[v][0], s[v][1]), fmaxf(s[v][2], s[v][3]));
            #pragma unroll
            for (int off = 8; off >= 1; off >>= 1)
                tm = fmaxf(tm, __shfl_xor_sync(0xffffffffu, tm, off));
            const float mn = fmaxf(m[v], tm);
            alpha[v] = __expf(m[v] - mn);
            m[v] = mn;
            float rs = 0.f;
            #pragma unroll
            for (int u = 0; u < 4; u++) {
                s[v][u] = __expf(s[v][u] - mn);
                rs += s[v][u];
            }
            #pragma unroll
            for (int off = 8; off >= 1; off >>= 1)
                rs += __shfl_xor_sync(0xffffffffu, rs, off);
            l[v] = l[v] * alpha[v] + rs;
        }
        #pragma unroll
        for (int v = 0; v < 4; v++)
            #pragma unroll
            for (int u = 0; u < 4; u++) O[v][u] *= alpha[v];

        __syncthreads();
        #pragma unroll
        for (int v = 0; v < 4; v++)
            *(float4*)&KB[ty * 4 + v][tx * 4] = make_float4(s[v][0], s[v][1], s[v][2], s[v][3]);
        __syncthreads();

        #pragma unroll 4
        for (int j = 0; j < 64; j++) {
            float4 v4 = *(float4*)&Vt[j][tx * 4];
            float vv[4] = {v4.x, v4.y, v4.z, v4.w};
            float pv[4];
            #pragma unroll
            for (int v = 0; v < 4; v++) pv[v] = KB[ty * 4 + v][j];
            #pragma unroll
            for (int v = 0; v < 4; v++)
                #pragma unroll
                for (int u = 0; u < 4; u++) O[v][u] += pv[v] * vv[u];
        }
    }

    #pragma unroll
    for (int v = 0; v < 4; v++) {
        const float inv = 1.0f / l[v];
        float4 o = make_float4(O[v][0] * inv, O[v][1] * inv, O[v][2] * inv, O[v][3] * inv);
        *(float4*)(g_attn + ((size_t)b * SS + qbase + ty * 4 + v) * DDIM + h * DH + tx * 4) = o;
    }
}

// ---------------- launch ----------------
extern "C" void kernel_launch(void* const* d_in, const int* in_sizes, int n_in,
                              void* d_out, int out_size)
{
    const float* hidden = (const float*)d_in[0];
    const float* mask   = (const float*)d_in[1];
    const float* pk     = (const float*)d_in[2];
    const float* pv     = (const float*)d_in[3];
    const float* Wq     = (const float*)d_in[4];
    const float* Wk     = (const float*)d_in[5];
    const float* Wv     = (const float*)d_in[6];
    const float* Wo     = (const float*)d_in[7];
    const float* rel    = (const float*)d_in[8];
    float* out = (float*)d_out;

    bias_init_kernel<<<(HH * 4127 + 255) / 256, 256>>>(rel);
    prefix_copy_kernel<<<(BB * HH * PFX * DH + 255) / 256, 256>>>(pk, pv);
    split_hidden_kernel<<<(BB * SS * DDIM + 255) / 256, 256>>>(hidden);
    split_w_kernel<<<dim3(32, 32, 4), 256>>>(Wq, Wk, Wv, Wo);
    gemm_qkv_mma<<<dim3(8, 32, 3), 256>>>();
    attn_kernel<<<dim3(SS / 64, HH, BB), 256>>>(mask);
    split_o_kernel<<<(BB * SS * DDIM + 255) / 256, 256>>>();
    gemm_o_mma<<<dim3(8, 32), 256>>>(out);
}

// round 5
// speedup vs baseline: 2.0318x; 1.6327x over previous
#include <cuda_runtime.h>
#include <cuda_bf16.h>
#include <math.h>
#include <stdint.h>

// Problem constants
#define BB   2
#define HH   16
#define SS   2048
#define DDIM 1024
#define DH   64
#define PFX  32
#define LKV  2080          // PFX + SS = 65 * 32
#define K3   3072          // 3x split-concatenated K
#define BIAS_STRIDE 4160
#define BIAS_OFF 2079

// ---------------- scratch (static device globals; no allocation) ----------------
__device__ float g_bias[HH * BIAS_STRIDE];                  // [h][rel+2079]
__device__ __nv_bfloat16 g_a3[(size_t)BB * SS * K3];        // hidden split [m][k3]
__device__ __nv_bfloat16 g_w3[(size_t)4 * DDIM * K3];       // Wq,Wk,Wv,Wo split+T [n][k3]
__device__ __nv_bfloat16 g_o3[(size_t)BB * SS * K3];        // attn-out split [m][k3]
__device__ __nv_bfloat16 g_qh[(size_t)BB * HH * SS * DH];   // [bh][s][d]
__device__ __nv_bfloat16 g_ql[(size_t)BB * HH * SS * DH];
__device__ __nv_bfloat16 g_kh[(size_t)BB * HH * LKV * DH];  // [bh][key][d]
__device__ __nv_bfloat16 g_kl[(size_t)BB * HH * LKV * DH];
__device__ __nv_bfloat16 g_vh[(size_t)BB * HH * LKV * DH];
__device__ __nv_bfloat16 g_vl[(size_t)BB * HH * LKV * DH];

// ======================= PTX helpers (sm_80-class only) =======================
__device__ __forceinline__ uint32_t smem_u32(const void* p) {
    uint32_t a;
    asm("{ .reg .u64 t; cvta.to.shared.u64 t, %1; cvt.u32.u64 %0, t; }" : "=r"(a) : "l"(p));
    return a;
}
__device__ __forceinline__ void cpa16(uint32_t dst, const void* src) {
    asm volatile("cp.async.cg.shared.global [%0], [%1], 16;" :: "r"(dst), "l"(src));
}
__device__ __forceinline__ void ldsm_x4(uint32_t* r, uint32_t addr) {
    asm volatile("ldmatrix.sync.aligned.m8n8.x4.shared.b16 {%0,%1,%2,%3}, [%4];"
                 : "=r"(r[0]), "=r"(r[1]), "=r"(r[2]), "=r"(r[3]) : "r"(addr));
}
__device__ __forceinline__ void ldsm_x4_t(uint32_t* r, uint32_t addr) {
    asm volatile("ldmatrix.sync.aligned.m8n8.x4.trans.shared.b16 {%0,%1,%2,%3}, [%4];"
                 : "=r"(r[0]), "=r"(r[1]), "=r"(r[2]), "=r"(r[3]) : "r"(addr));
}
__device__ __forceinline__ void mma16816(float* d, const uint32_t* a, const uint32_t* b) {
    asm volatile("mma.sync.aligned.m16n8k16.row.col.f32.bf16.bf16.f32 "
                 "{%0,%1,%2,%3}, {%4,%5,%6,%7}, {%8,%9}, {%0,%1,%2,%3};"
                 : "+f"(d[0]), "+f"(d[1]), "+f"(d[2]), "+f"(d[3])
                 : "r"(a[0]), "r"(a[1]), "r"(a[2]), "r"(a[3]), "r"(b[0]), "r"(b[1]));
}
__device__ __forceinline__ uint32_t pkb2(__nv_bfloat16 a, __nv_bfloat16 b) {
    uint16_t ua = *(uint16_t*)&a, ub = *(uint16_t*)&b;
    return (uint32_t)ua | ((uint32_t)ub << 16);
}
// GEMM smem swizzle: rows of 64B (32 bf16), quad = 16B unit
__device__ __forceinline__ uint32_t sw_addr(uint32_t base, int r, int k) {
    int quad = k >> 3;
    int sw   = quad ^ ((r >> 1) & 3);
    return base + r * 64 + sw * 16 + (k & 7) * 2;
}

// ---------------- bias table init ----------------
__global__ void bias_init_kernel(const float* __restrict__ rel_table)
{
    int idx = blockIdx.x * blockDim.x + threadIdx.x;
    const int total = HH * 4127;
    if (idx >= total) return;
    int h   = idx / 4127;
    int r   = idx - h * 4127;
    int rel = r - BIAS_OFF;

    int ret = (rel > 0) ? 16 : 0;
    int n   = rel < 0 ? -rel : rel;
    int bkt;
    if (n < 8) {
        bkt = n;
    } else {
        float nf = (float)n;
        int vl = 8 + (int)(logf(nf * 0.125f) / 2.772588722239781f * 8.0f);
        bkt = vl < 15 ? vl : 15;
    }
    bkt += ret;
    g_bias[h * BIAS_STRIDE + r] = rel_table[bkt * HH + h];
}

// ---------------- prefix K/V copy (fp32 -> bf16 hi/lo) ----------------
__global__ void prefix_copy_kernel(const float* __restrict__ pk,
                                   const float* __restrict__ pv)
{
    int idx = blockIdx.x * blockDim.x + threadIdx.x;
    const int total = BB * HH * PFX * DH;
    if (idx >= total) return;
    int d  = idx & 63;
    int p  = (idx >> 6) & 31;
    int bh = idx >> 11;
    size_t o = ((size_t)bh * LKV + p) * DH + d;
    float kx = pk[idx], vx = pv[idx];
    __nv_bfloat16 khf = __float2bfloat16(kx);
    __nv_bfloat16 vhf = __float2bfloat16(vx);
    g_kh[o] = khf;
    g_kl[o] = __float2bfloat16(kx - __bfloat162float(khf));
    g_vh[o] = vhf;
    g_vl[o] = __float2bfloat16(vx - __bfloat162float(vhf));
}

// ---------------- split kernels (bf16 hi/lo, 3x concat along K) ----------------
__global__ void split_hidden_kernel(const float* __restrict__ src)
{
    int i = blockIdx.x * blockDim.x + threadIdx.x;
    const int n = BB * SS * DDIM;
    if (i >= n) return;
    float x = src[i];
    __nv_bfloat16 h = __float2bfloat16(x);
    __nv_bfloat16 l = __float2bfloat16(x - __bfloat162float(h));
    size_t b = (size_t)(i >> 10) * K3 + (i & 1023);
    g_a3[b]        = h;
    g_a3[b + 1024] = h;
    g_a3[b + 2048] = l;
}

// W [k][n] fp32 -> W3 [n][k3] bf16 = [hi | lo | hi] (transposed)
__global__ __launch_bounds__(256) void split_w_kernel(const float* __restrict__ Wq,
                                                      const float* __restrict__ Wk,
                                                      const float* __restrict__ Wv,
                                                      const float* __restrict__ Wo)
{
    __shared__ float tile[32][33];
    const int z = blockIdx.z;
    const float* W = (z == 0) ? Wq : (z == 1) ? Wk : (z == 2) ? Wv : Wo;
    __nv_bfloat16* dst = g_w3 + (size_t)z * DDIM * K3;

    const int n0 = blockIdx.x * 32, k0 = blockIdx.y * 32;
    const int tx = threadIdx.x & 31, ty0 = threadIdx.x >> 5;
    #pragma unroll
    for (int r = 0; r < 4; r++) {
        int ty = ty0 + r * 8;
        tile[ty][tx] = W[(size_t)(k0 + ty) * DDIM + n0 + tx];
    }
    __syncthreads();
    #pragma unroll
    for (int r = 0; r < 4; r++) {
        int ty = ty0 + r * 8;
        float x = tile[tx][ty];
        __nv_bfloat16 h = __float2bfloat16(x);
        __nv_bfloat16 l = __float2bfloat16(x - __bfloat162float(h));
        size_t b = (size_t)(n0 + ty) * K3 + (k0 + tx);
        dst[b]        = h;
        dst[b + 1024] = l;
        dst[b + 2048] = h;
    }
}

// ---------------- mma.sync bf16 GEMM: C[4096 x 1024] = A3 * W3^T ----------------
#define CHUNK 32
#define NSTG 3
#define STG_BYTES 16384

__device__ __forceinline__ void gemm_load_chunk(uint32_t sb,
        const __nv_bfloat16* __restrict__ Ag, const __nv_bfloat16* __restrict__ Bg,
        int mblock, int nblock, int c)
{
    const int t = threadIdx.x;
    const int st = c % NSTG;
    uint32_t ab = sb + st * STG_BYTES;
    uint32_t bb = ab + 8192;
    #pragma unroll
    for (int i = 0; i < 2; i++) {
        int idx = t + i * 256;
        int r = idx >> 2, q = idx & 3;
        uint32_t soff = (uint32_t)(r * 64 + ((q ^ ((r >> 1) & 3)) << 4));
        const char* as = (const char*)(Ag + (size_t)(mblock + r) * K3 + c * CHUNK + q * 8);
        const char* bs = (const char*)(Bg + (size_t)(nblock + r) * K3 + c * CHUNK + q * 8);
        cpa16(ab + soff, as);
        cpa16(bb + soff, bs);
    }
    asm volatile("cp.async.commit_group;" ::: "memory");
}

__device__ __forceinline__ void gemm_mma_body(const __nv_bfloat16* __restrict__ Ag,
                                              const __nv_bfloat16* __restrict__ Bg,
                                              int mblock, int nblock, int flavor,
                                              float* __restrict__ outp)
{
    __shared__ __align__(128) char smbuf[NSTG * STG_BYTES];
    uint32_t sb = smem_u32(smbuf);
    const int t    = threadIdx.x;
    const int lane = t & 31;
    const int w    = t >> 5;
    const int wm   = w >> 1;
    const int wn   = w & 1;

    float acc[2][8][4];
    #pragma unroll
    for (int f = 0; f < 2; f++)
        #pragma unroll
        for (int p = 0; p < 8; p++)
            #pragma unroll
            for (int e = 0; e < 4; e++) acc[f][p][e] = 0.f;

    const int NCH = K3 / CHUNK;   // 96

    gemm_load_chunk(sb, Ag, Bg, mblock, nblock, 0);
    gemm_load_chunk(sb, Ag, Bg, mblock, nblock, 1);

    for (int c = 0; c < NCH; c++) {
        if (c < NCH - 1) asm volatile("cp.async.wait_group 1;" ::: "memory");
        else             asm volatile("cp.async.wait_group 0;" ::: "memory");
        __syncthreads();

        uint32_t ab = sb + (c % NSTG) * STG_BYTES;
        uint32_t bb = ab + 8192;

        #pragma unroll
        for (int ks = 0; ks < 2; ks++) {
            uint32_t afr[2][4];
            #pragma unroll
            for (int f = 0; f < 2; f++) {
                int r = wm * 32 + f * 16 + (lane & 15);
                int k = ks * 16 + (lane >> 4) * 8;
                ldsm_x4(afr[f], sw_addr(ab, r, k));
            }
            uint32_t bfr[8][2];
            #pragma unroll
            for (int p = 0; p < 4; p++) {
                int n = wn * 64 + p * 16 + ((lane >> 4) & 1) * 8 + (lane & 7);
                int k = ks * 16 + ((lane >> 3) & 1) * 8;
                uint32_t r4[4];
                ldsm_x4(r4, sw_addr(bb, n, k));
                bfr[p * 2][0]     = r4[0];
                bfr[p * 2][1]     = r4[1];
                bfr[p * 2 + 1][0] = r4[2];
                bfr[p * 2 + 1][1] = r4[3];
            }
            #pragma unroll
            for (int f = 0; f < 2; f++)
                #pragma unroll
                for (int p = 0; p < 8; p++)
                    mma16816(acc[f][p], afr[f], bfr[p]);
        }
        __syncthreads();
        if (c + 2 < NCH) gemm_load_chunk(sb, Ag, Bg, mblock, nblock, c + 2);
    }

    // epilogue: m = .. + (lane>>2) + e2*8 ; n pair = .. + (lane&3)*2 + {0,1}
    #pragma unroll
    for (int f = 0; f < 2; f++) {
        #pragma unroll
        for (int p = 0; p < 8; p++) {
            #pragma unroll
            for (int e2 = 0; e2 < 2; e2++) {
                int m  = mblock + wm * 32 + f * 16 + (lane >> 2) + e2 * 8;
                int n0 = nblock + wn * 64 + p * 8 + ((lane & 3) << 1);
                float v0 = acc[f][p][e2 * 2], v1 = acc[f][p][e2 * 2 + 1];
                if (flavor == 3) {
                    outp[(size_t)m * DDIM + n0]     = v0;
                    outp[(size_t)m * DDIM + n0 + 1] = v1;
                } else {
                    __nv_bfloat16 h0 = __float2bfloat16(v0), h1 = __float2bfloat16(v1);
                    uint32_t hi = pkb2(h0, h1);
                    uint32_t lo = pkb2(__float2bfloat16(v0 - __bfloat162float(h0)),
                                       __float2bfloat16(v1 - __bfloat162float(h1)));
                    int b0 = m >> 11, s = m & 2047, hh = n0 >> 6, d = n0 & 63;
                    int bh = b0 * HH + hh;
                    if (flavor == 0) {
                        size_t o = ((size_t)bh * SS + s) * DH + d;
                        *(uint32_t*)(g_qh + o) = hi;
                        *(uint32_t*)(g_ql + o) = lo;
                    } else {
                        size_t o = ((size_t)bh * LKV + PFX + s) * DH + d;
                        if (flavor == 1) {
                            *(uint32_t*)(g_kh + o) = hi;
                            *(uint32_t*)(g_kl + o) = lo;
                        } else {
                            *(uint32_t*)(g_vh + o) = hi;
                            *(uint32_t*)(g_vl + o) = lo;
                        }
                    }
                }
            }
        }
    }
}

__global__ __launch_bounds__(256) void gemm_qkv_mma()
{
    const int z = blockIdx.z;
    gemm_mma_body(g_a3, g_w3 + (size_t)z * DDIM * K3,
                  blockIdx.y * 128, blockIdx.x * 128, z, nullptr);
}

__global__ __launch_bounds__(256) void gemm_o_mma(float* __restrict__ out)
{
    gemm_mma_body(g_o3, g_w3 + (size_t)3 * DDIM * K3,
                  blockIdx.y * 128, blockIdx.x * 128, 3, out);
}

// ---------------- mma.sync flash attention ----------------
// 256 thr / 8 warps; Q-tile 128 (warp = 16 rows); KV-tile 32; 2-stage cp.async.
// Stage layout: Khi(4K) Klo(4K) Vhi(4K) Vlo(4K) = 16KB; rows of 128B, chunk^=(row&7).
__device__ __forceinline__ void attn_load_kv(int t, int bh, int kt, uint32_t base)
{
    const int row = t >> 3, c = t & 7;
    uint32_t off = (uint32_t)(row * 128 + ((c ^ (row & 7)) << 4));
    size_t goff = ((size_t)bh * LKV + kt * 32 + row) * DH + c * 8;
    cpa16(base + off,         g_kh + goff);
    cpa16(base + 4096 + off,  g_kl + goff);
    cpa16(base + 8192 + off,  g_vh + goff);
    cpa16(base + 12288 + off, g_vl + goff);
    asm volatile("cp.async.commit_group;" ::: "memory");
}

__global__ __launch_bounds__(256) void attn_mma_kernel(const float* __restrict__ mask)
{
    __shared__ __align__(1024) char kvsm[2][16384];
    const int t = threadIdx.x, lane = t & 31, w = t >> 5;
    const int g = lane >> 2, tc = lane & 3;
    const int h = blockIdx.y, b = blockIdx.z, bh = b * HH + h;
    const int qb = blockIdx.x * 128;
    const int m0 = qb + w * 16;

    // Q fragments (a0:(g,k0) a1:(g+8,k0) a2:(g,k0+8) a3:(g+8,k0+8)), direct LDG
    uint32_t qh[4][4], ql[4][4];
    {
        const __nv_bfloat16* qhp = g_qh + ((size_t)bh * SS + m0) * DH;
        const __nv_bfloat16* qlp = g_ql + ((size_t)bh * SS + m0) * DH;
        #pragma unroll
        for (int j = 0; j < 4; j++)
            #pragma unroll
            for (int e = 0; e < 4; e++) {
                int r = g + (e & 1) * 8;
                int k = j * 16 + tc * 2 + (e >> 1) * 8;
                qh[j][e] = *(const uint32_t*)(qhp + (size_t)r * DH + k);
                ql[j][e] = *(const uint32_t*)(qlp + (size_t)r * DH + k);
            }
    }

    float ofr[8][4];
    #pragma unroll
    for (int i = 0; i < 8; i++)
        #pragma unroll
        for (int e = 0; e < 4; e++) ofr[i][e] = 0.f;
    float mrow[2] = {-INFINITY, -INFINITY};
    float lrow[2] = {0.f, 0.f};

    const float* maskb = mask + b * SS;
    const float* biash = g_bias + h * BIAS_STRIDE;

    attn_load_kv(t, bh, 0, smem_u32(&kvsm[0][0]));

    const int NT = LKV / 32;   // 65
    for (int kt = 0; kt < NT; kt++) {
        asm volatile("cp.async.wait_group 0;" ::: "memory");
        __syncthreads();
        if (kt + 1 < NT) attn_load_kv(t, bh, kt + 1, smem_u32(&kvsm[(kt + 1) & 1][0]));

        uint32_t kbb = smem_u32(&kvsm[kt & 1][0]);
        uint32_t vbb = kbb + 8192;
        const int kb = kt * 32;

        // ---- scores: S = Qhi Khi^T + Qhi Klo^T + Qlo Khi^T ----
        float sfr[4][4];
        #pragma unroll
        for (int i = 0; i < 4; i++)
            #pragma unroll
            for (int e = 0; e < 4; e++) sfr[i][e] = 0.f;

        #pragma unroll
        for (int j = 0; j < 4; j++) {
            #pragma unroll
            for (int gk2 = 0; gk2 < 2; gk2++) {
                int row = gk2 * 16 + ((lane >> 4) << 3) + (lane & 7);
                int ch  = 2 * j + ((lane >> 3) & 1);
                uint32_t ah = kbb + row * 128 + ((ch ^ (row & 7)) << 4);
                uint32_t kh4[4], kl4[4];
                ldsm_x4(kh4, ah);
                ldsm_x4(kl4, ah + 4096);
                mma16816(sfr[2 * gk2],     qh[j], kh4);
                mma16816(sfr[2 * gk2 + 1], qh[j], kh4 + 2);
                mma16816(sfr[2 * gk2],     qh[j], kl4);
                mma16816(sfr[2 * gk2 + 1], qh[j], kl4 + 2);
                mma16816(sfr[2 * gk2],     ql[j], kh4);
                mma16816(sfr[2 * gk2 + 1], ql[j], kh4 + 2);
            }
        }

        // ---- bias + mask ----
        #pragma unroll
        for (int grp = 0; grp < 4; grp++) {
            int key0 = kb + grp * 8 + tc * 2;
            float mv0 = (key0 >= PFX)     ? maskb[key0 - PFX]     : 0.f;
            float mv1 = (key0 + 1 >= PFX) ? maskb[key0 + 1 - PFX] : 0.f;
            const float* bp = biash + (key0 - (m0 + g) + (BIAS_OFF - PFX));
            sfr[grp][0] += bp[0] + mv0;
            sfr[grp][1] += bp[1] + mv1;
            sfr[grp][2] += bp[-8] + mv0;
            sfr[grp][3] += bp[-7] + mv1;
        }

        // ---- online softmax (rows g and g+8; quad reduce over lanes xor 1,2) ----
        #pragma unroll
        for (int row = 0; row < 2; row++) {
            float mx = sfr[0][row * 2];
            #pragma unroll
            for (int grp = 0; grp < 4; grp++) {
                mx = fmaxf(mx, sfr[grp][row * 2]);
                mx = fmaxf(mx, sfr[grp][row * 2 + 1]);
            }
            mx = fmaxf(mx, __shfl_xor_sync(0xffffffffu, mx, 1));
            mx = fmaxf(mx, __shfl_xor_sync(0xffffffffu, mx, 2));
            float mn = fmaxf(mrow[row], mx);
            float alpha = __expf(mrow[row] - mn);
            mrow[row] = mn;
            float sum = 0.f;
            #pragma unroll
            for (int grp = 0; grp < 4; grp++) {
                float p0 = __expf(sfr[grp][row * 2] - mn);
                float p1 = __expf(sfr[grp][row * 2 + 1] - mn);
                sfr[grp][row * 2] = p0;
                sfr[grp][row * 2 + 1] = p1;
                sum += p0 + p1;
            }
            sum += __shfl_xor_sync(0xffffffffu, sum, 1);
            sum += __shfl_xor_sync(0xffffffffu, sum, 2);
            lrow[row] = lrow[row] * alpha + sum;
            #pragma unroll
            for (int gd = 0; gd < 8; gd++) {
                ofr[gd][row * 2]     *= alpha;
                ofr[gd][row * 2 + 1] *= alpha;
            }
        }

        // ---- P fragments (C-frag is A-frag; split hi/lo) ----
        uint32_t phi[2][4], plo[2][4];
        #pragma unroll
        for (int jk = 0; jk < 2; jk++) {
            #pragma unroll
            for (int e = 0; e < 4; e++) {
                int grp = 2 * jk + (e >> 1);
                int i0  = (e & 1) * 2;
                float p0 = sfr[grp][i0], p1 = sfr[grp][i0 + 1];
                __nv_bfloat16 h0 = __float2bfloat16(p0), h1 = __float2bfloat16(p1);
                phi[jk][e] = pkb2(h0, h1);
                plo[jk][e] = pkb2(__float2bfloat16(p0 - __bfloat162float(h0)),
                                  __float2bfloat16(p1 - __bfloat162float(h1)));
            }
        }

        // ---- PV: O += Phi Vhi + Phi Vlo + Plo Vhi (V via ldmatrix.trans) ----
        #pragma unroll
        for (int jk = 0; jk < 2; jk++) {
            #pragma unroll
            for (int gd2 = 0; gd2 < 4; gd2++) {
                int row = jk * 16 + (((lane >> 3) & 1) << 3) + (lane & 7);
                int ch  = 2 * gd2 + (lane >> 4);
                uint32_t av = vbb + row * 128 + ((ch ^ (row & 7)) << 4);
                uint32_t vh4[4], vl4[4];
                ldsm_x4_t(vh4, av);
                ldsm_x4_t(vl4, av + 4096);
                mma16816(ofr[2 * gd2],     phi[jk], vh4);
                mma16816(ofr[2 * gd2 + 1], phi[jk], vh4 + 2);
                mma16816(ofr[2 * gd2],     phi[jk], vl4);
                mma16816(ofr[2 * gd2 + 1], phi[jk], vl4 + 2);
                mma16816(ofr[2 * gd2],     plo[jk], vh4);
                mma16816(ofr[2 * gd2 + 1], plo[jk], vh4 + 2);
            }
        }
    }

    // ---- epilogue: normalize, split hi/lo, write o3 = [hi|hi|lo] ----
    float inv0 = 1.f / lrow[0], inv1 = 1.f / lrow[1];
    #pragma unroll
    for (int gd = 0; gd < 8; gd++) {
        int d0 = gd * 8 + tc * 2;
        int k  = h * 64 + d0;
        #pragma unroll
        for (int row = 0; row < 2; row++) {
            float v0 = ofr[gd][row * 2]     * (row ? inv1 : inv0);
            float v1 = ofr[gd][row * 2 + 1] * (row ? inv1 : inv0);
            __nv_bfloat16 h0 = __float2bfloat16(v0), h1 = __float2bfloat16(v1);
            uint32_t hi = pkb2(h0, h1);
            uint32_t lo = pkb2(__float2bfloat16(v0 - __bfloat162float(h0)),
                               __float2bfloat16(v1 - __bfloat162float(h1)));
            size_t rbase = ((size_t)(b * SS + m0 + g + row * 8)) * K3 + k;
            *(uint32_t*)(g_o3 + rbase)        = hi;
            *(uint32_t*)(g_o3 + rbase + 1024) = hi;
            *(uint32_t*)(g_o3 + rbase + 2048) = lo;
        }
    }
}

// ---------------- launch ----------------
extern "C" void kernel_launch(void* const* d_in, const int* in_sizes, int n_in,
                              void* d_out, int out_size)
{
    const float* hidden = (const float*)d_in[0];
    const float* mask   = (const float*)d_in[1];
    const float* pk     = (const float*)d_in[2];
    const float* pv     = (const float*)d_in[3];
    const float* Wq     = (const float*)d_in[4];
    const float* Wk     = (const float*)d_in[5];
    const float* Wv     = (const float*)d_in[6];
    const float* Wo     = (const float*)d_in[7];
    const float* rel    = (const float*)d_in[8];
    float* out = (float*)d_out;

    bias_init_kernel<<<(HH * 4127 + 255) / 256, 256>>>(rel);
    prefix_copy_kernel<<<(BB * HH * PFX * DH + 255) / 256, 256>>>(pk, pv);
    split_hidden_kernel<<<(BB * SS * DDIM + 255) / 256, 256>>>(hidden);
    split_w_kernel<<<dim3(32, 32, 4), 256>>>(Wq, Wk, Wv, Wo);
    gemm_qkv_mma<<<dim3(8, 32, 3), 256>>>();
    attn_mma_kernel<<<dim3(SS / 128, HH, BB), 256>>>(mask);
    gemm_o_mma<<<dim3(8, 32), 256>>>(out);
}

// round 6
// speedup vs baseline: 2.3522x; 1.1577x over previous
#include <cuda_runtime.h>
#include <cuda_bf16.h>
#include <math.h>
#include <stdint.h>

// Problem constants
#define BB   2
#define HH   16
#define SS   2048
#define DDIM 1024
#define DH   64
#define PFX  32
#define LKV  2080          // PFX + SS = 65 * 32
#define K3   3072          // 3x split-concatenated K
#define BIAS_STRIDE 4160
#define BIAS_OFF 2079

// ---------------- scratch (static device globals; no allocation) ----------------
__device__ float g_bias[HH * BIAS_STRIDE];                  // [h][rel+2079]
__device__ __nv_bfloat16 g_a3[(size_t)BB * SS * K3];        // hidden split [m][k3]
__device__ __nv_bfloat16 g_w3[(size_t)4 * DDIM * K3];       // Wq,Wk,Wv,Wo split+T [n][k3]
__device__ __nv_bfloat16 g_o3[(size_t)BB * SS * K3];        // attn-out split [m][k3]
__device__ __nv_bfloat16 g_qh[(size_t)BB * HH * SS * DH];   // [bh][s][d]
__device__ __nv_bfloat16 g_ql[(size_t)BB * HH * SS * DH];
__device__ __nv_bfloat16 g_kh[(size_t)BB * HH * LKV * DH];  // [bh][key][d]
__device__ __nv_bfloat16 g_kl[(size_t)BB * HH * LKV * DH];
__device__ __nv_bfloat16 g_vh[(size_t)BB * HH * LKV * DH];
__device__ __nv_bfloat16 g_vl[(size_t)BB * HH * LKV * DH];

// ======================= PTX helpers (sm_80-class only) =======================
__device__ __forceinline__ uint32_t smem_u32(const void* p) {
    uint32_t a;
    asm("{ .reg .u64 t; cvta.to.shared.u64 t, %1; cvt.u32.u64 %0, t; }" : "=r"(a) : "l"(p));
    return a;
}
__device__ __forceinline__ void cpa16(uint32_t dst, const void* src) {
    asm volatile("cp.async.cg.shared.global [%0], [%1], 16;" :: "r"(dst), "l"(src));
}
__device__ __forceinline__ void ldsm_x4(uint32_t* r, uint32_t addr) {
    asm volatile("ldmatrix.sync.aligned.m8n8.x4.shared.b16 {%0,%1,%2,%3}, [%4];"
                 : "=r"(r[0]), "=r"(r[1]), "=r"(r[2]), "=r"(r[3]) : "r"(addr));
}
__device__ __forceinline__ void ldsm_x4_t(uint32_t* r, uint32_t addr) {
    asm volatile("ldmatrix.sync.aligned.m8n8.x4.trans.shared.b16 {%0,%1,%2,%3}, [%4];"
                 : "=r"(r[0]), "=r"(r[1]), "=r"(r[2]), "=r"(r[3]) : "r"(addr));
}
__device__ __forceinline__ void mma16816(float* d, const uint32_t* a, const uint32_t* b) {
    asm volatile("mma.sync.aligned.m16n8k16.row.col.f32.bf16.bf16.f32 "
                 "{%0,%1,%2,%3}, {%4,%5,%6,%7}, {%8,%9}, {%0,%1,%2,%3};"
                 : "+f"(d[0]), "+f"(d[1]), "+f"(d[2]), "+f"(d[3])
                 : "r"(a[0]), "r"(a[1]), "r"(a[2]), "r"(a[3]), "r"(b[0]), "r"(b[1]));
}
__device__ __forceinline__ uint32_t pkb2(__nv_bfloat16 a, __nv_bfloat16 b) {
    uint16_t ua = *(uint16_t*)&a, ub = *(uint16_t*)&b;
    return (uint32_t)ua | ((uint32_t)ub << 16);
}
// GEMM smem swizzle: rows of 64B (32 bf16), quad = 16B unit
__device__ __forceinline__ uint32_t sw_addr(uint32_t base, int r, int k) {
    int quad = k >> 3;
    int sw   = quad ^ ((r >> 1) & 3);
    return base + r * 64 + sw * 16 + (k & 7) * 2;
}

// ---------------- bias table init ----------------
__global__ void bias_init_kernel(const float* __restrict__ rel_table)
{
    int idx = blockIdx.x * blockDim.x + threadIdx.x;
    const int total = HH * 4127;
    if (idx >= total) return;
    int h   = idx / 4127;
    int r   = idx - h * 4127;
    int rel = r - BIAS_OFF;

    int ret = (rel > 0) ? 16 : 0;
    int n   = rel < 0 ? -rel : rel;
    int bkt;
    if (n < 8) {
        bkt = n;
    } else {
        float nf = (float)n;
        int vl = 8 + (int)(logf(nf * 0.125f) / 2.772588722239781f * 8.0f);
        bkt = vl < 15 ? vl : 15;
    }
    bkt += ret;
    g_bias[h * BIAS_STRIDE + r] = rel_table[bkt * HH + h];
}

// ---------------- prefix K/V copy (fp32 -> bf16 hi/lo) ----------------
__global__ void prefix_copy_kernel(const float* __restrict__ pk,
                                   const float* __restrict__ pv)
{
    int idx = blockIdx.x * blockDim.x + threadIdx.x;
    const int total = BB * HH * PFX * DH;
    if (idx >= total) return;
    int d  = idx & 63;
    int p  = (idx >> 6) & 31;
    int bh = idx >> 11;
    size_t o = ((size_t)bh * LKV + p) * DH + d;
    float kx = pk[idx], vx = pv[idx];
    __nv_bfloat16 khf = __float2bfloat16(kx);
    __nv_bfloat16 vhf = __float2bfloat16(vx);
    g_kh[o] = khf;
    g_kl[o] = __float2bfloat16(kx - __bfloat162float(khf));
    g_vh[o] = vhf;
    g_vl[o] = __float2bfloat16(vx - __bfloat162float(vhf));
}

// ---------------- split kernels (bf16 hi/lo, 3x concat along K) ----------------
__global__ void split_hidden_kernel(const float* __restrict__ src)
{
    int i = blockIdx.x * blockDim.x + threadIdx.x;
    const int n = BB * SS * DDIM;
    if (i >= n) return;
    float x = src[i];
    __nv_bfloat16 h = __float2bfloat16(x);
    __nv_bfloat16 l = __float2bfloat16(x - __bfloat162float(h));
    size_t b = (size_t)(i >> 10) * K3 + (i & 1023);
    g_a3[b]        = h;
    g_a3[b + 1024] = h;
    g_a3[b + 2048] = l;
}

// W [k][n] fp32 -> W3 [n][k3] bf16 = [hi | lo | hi] (transposed)
__global__ __launch_bounds__(256) void split_w_kernel(const float* __restrict__ Wq,
                                                      const float* __restrict__ Wk,
                                                      const float* __restrict__ Wv,
                                                      const float* __restrict__ Wo)
{
    __shared__ float tile[32][33];
    const int z = blockIdx.z;
    const float* W = (z == 0) ? Wq : (z == 1) ? Wk : (z == 2) ? Wv : Wo;
    __nv_bfloat16* dst = g_w3 + (size_t)z * DDIM * K3;

    const int n0 = blockIdx.x * 32, k0 = blockIdx.y * 32;
    const int tx = threadIdx.x & 31, ty0 = threadIdx.x >> 5;
    #pragma unroll
    for (int r = 0; r < 4; r++) {
        int ty = ty0 + r * 8;
        tile[ty][tx] = W[(size_t)(k0 + ty) * DDIM + n0 + tx];
    }
    __syncthreads();
    #pragma unroll
    for (int r = 0; r < 4; r++) {
        int ty = ty0 + r * 8;
        float x = tile[tx][ty];
        __nv_bfloat16 h = __float2bfloat16(x);
        __nv_bfloat16 l = __float2bfloat16(x - __bfloat162float(h));
        size_t b = (size_t)(n0 + ty) * K3 + (k0 + tx);
        dst[b]        = h;
        dst[b + 1024] = l;
        dst[b + 2048] = h;
    }
}

// ---------------- mma.sync bf16 GEMM: C[4096 x 1024] = A3 * W3^T ----------------
#define CHUNK 32
#define NSTG 3
#define STG_BYTES 16384

__device__ __forceinline__ void gemm_load_chunk(uint32_t sb,
        const __nv_bfloat16* __restrict__ Ag, const __nv_bfloat16* __restrict__ Bg,
        int mblock, int nblock, int c)
{
    const int t = threadIdx.x;
    const int st = c % NSTG;
    uint32_t ab = sb + st * STG_BYTES;
    uint32_t bb = ab + 8192;
    #pragma unroll
    for (int i = 0; i < 2; i++) {
        int idx = t + i * 256;
        int r = idx >> 2, q = idx & 3;
        uint32_t soff = (uint32_t)(r * 64 + ((q ^ ((r >> 1) & 3)) << 4));
        const char* as = (const char*)(Ag + (size_t)(mblock + r) * K3 + c * CHUNK + q * 8);
        const char* bs = (const char*)(Bg + (size_t)(nblock + r) * K3 + c * CHUNK + q * 8);
        cpa16(ab + soff, as);
        cpa16(bb + soff, bs);
    }
    asm volatile("cp.async.commit_group;" ::: "memory");
}

__device__ __forceinline__ void gemm_mma_body(const __nv_bfloat16* __restrict__ Ag,
                                              const __nv_bfloat16* __restrict__ Bg,
                                              int mblock, int nblock, int flavor,
                                              float* __restrict__ outp)
{
    __shared__ __align__(128) char smbuf[NSTG * STG_BYTES];
    uint32_t sb = smem_u32(smbuf);
    const int t    = threadIdx.x;
    const int lane = t & 31;
    const int w    = t >> 5;
    const int wm   = w >> 1;
    const int wn   = w & 1;

    float acc[2][8][4];
    #pragma unroll
    for (int f = 0; f < 2; f++)
        #pragma unroll
        for (int p = 0; p < 8; p++)
            #pragma unroll
            for (int e = 0; e < 4; e++) acc[f][p][e] = 0.f;

    const int NCH = K3 / CHUNK;   // 96

    gemm_load_chunk(sb, Ag, Bg, mblock, nblock, 0);
    gemm_load_chunk(sb, Ag, Bg, mblock, nblock, 1);

    for (int c = 0; c < NCH; c++) {
        if (c < NCH - 1) asm volatile("cp.async.wait_group 1;" ::: "memory");
        else             asm volatile("cp.async.wait_group 0;" ::: "memory");
        __syncthreads();
        // single sync per iter: all warps have finished reading stage (c-1)%NSTG
        // (== (c+2)%NSTG) during iter c-1, so the load below is safe and
        // overlaps with this iteration's MMA work.
        if (c + 2 < NCH) gemm_load_chunk(sb, Ag, Bg, mblock, nblock, c + 2);

        uint32_t ab = sb + (c % NSTG) * STG_BYTES;
        uint32_t bb = ab + 8192;

        #pragma unroll
        for (int ks = 0; ks < 2; ks++) {
            uint32_t afr[2][4];
            #pragma unroll
            for (int f = 0; f < 2; f++) {
                int r = wm * 32 + f * 16 + (lane & 15);
                int k = ks * 16 + (lane >> 4) * 8;
                ldsm_x4(afr[f], sw_addr(ab, r, k));
            }
            uint32_t bfr[8][2];
            #pragma unroll
            for (int p = 0; p < 4; p++) {
                int n = wn * 64 + p * 16 + ((lane >> 4) & 1) * 8 + (lane & 7);
                int k = ks * 16 + ((lane >> 3) & 1) * 8;
                uint32_t r4[4];
                ldsm_x4(r4, sw_addr(bb, n, k));
                bfr[p * 2][0]     = r4[0];
                bfr[p * 2][1]     = r4[1];
                bfr[p * 2 + 1][0] = r4[2];
                bfr[p * 2 + 1][1] = r4[3];
            }
            #pragma unroll
            for (int f = 0; f < 2; f++)
                #pragma unroll
                for (int p = 0; p < 8; p++)
                    mma16816(acc[f][p], afr[f], bfr[p]);
        }
    }

    // epilogue: m = .. + (lane>>2) + e2*8 ; n pair = .. + (lane&3)*2 + {0,1}
    #pragma unroll
    for (int f = 0; f < 2; f++) {
        #pragma unroll
        for (int p = 0; p < 8; p++) {
            #pragma unroll
            for (int e2 = 0; e2 < 2; e2++) {
                int m  = mblock + wm * 32 + f * 16 + (lane >> 2) + e2 * 8;
                int n0 = nblock + wn * 64 + p * 8 + ((lane & 3) << 1);
                float v0 = acc[f][p][e2 * 2], v1 = acc[f][p][e2 * 2 + 1];
                if (flavor == 3) {
                    outp[(size_t)m * DDIM + n0]     = v0;
                    outp[(size_t)m * DDIM + n0 + 1] = v1;
                } else {
                    __nv_bfloat16 h0 = __float2bfloat16(v0), h1 = __float2bfloat16(v1);
                    uint32_t hi = pkb2(h0, h1);
                    uint32_t lo = pkb2(__float2bfloat16(v0 - __bfloat162float(h0)),
                                       __float2bfloat16(v1 - __bfloat162float(h1)));
                    int b0 = m >> 11, s = m & 2047, hh = n0 >> 6, d = n0 & 63;
                    int bh = b0 * HH + hh;
                    if (flavor == 0) {
                        size_t o = ((size_t)bh * SS + s) * DH + d;
                        *(uint32_t*)(g_qh + o) = hi;
                        *(uint32_t*)(g_ql + o) = lo;
                    } else {
                        size_t o = ((size_t)bh * LKV + PFX + s) * DH + d;
                        if (flavor == 1) {
                            *(uint32_t*)(g_kh + o) = hi;
                            *(uint32_t*)(g_kl + o) = lo;
                        } else {
                            *(uint32_t*)(g_vh + o) = hi;
                            *(uint32_t*)(g_vl + o) = lo;
                        }
                    }
                }
            }
        }
    }
}

__global__ __launch_bounds__(256) void gemm_qkv_mma()
{
    const int z = blockIdx.z;
    gemm_mma_body(g_a3, g_w3 + (size_t)z * DDIM * K3,
                  blockIdx.y * 128, blockIdx.x * 128, z, nullptr);
}

__global__ __launch_bounds__(256) void gemm_o_mma(float* __restrict__ out)
{
    gemm_mma_body(g_o3, g_w3 + (size_t)3 * DDIM * K3,
                  blockIdx.y * 128, blockIdx.x * 128, 3, out);
}

// ---------------- mma.sync flash attention ----------------
// 128 thr / 4 warps; Q-tile 64 (warp = 16 rows); KV-tile 32; 2-stage cp.async.
// smem 32KB -> ~3 CTAs/SM for latency hiding.
// Stage layout: Khi(4K) Klo(4K) Vhi(4K) Vlo(4K) = 16KB; rows of 128B, chunk^=(row&7).
__device__ __forceinline__ void attn_load_kv(int t, int bh, int kt, uint32_t base)
{
    #pragma unroll
    for (int i = 0; i < 2; i++) {
        const int row = (t >> 3) + i * 16;
        const int c = t & 7;
        uint32_t off = (uint32_t)(row * 128 + ((c ^ (row & 7)) << 4));
        size_t goff = ((size_t)bh * LKV + kt * 32 + row) * DH + c * 8;
        cpa16(base + off,         g_kh + goff);
        cpa16(base + 4096 + off,  g_kl + goff);
        cpa16(base + 8192 + off,  g_vh + goff);
        cpa16(base + 12288 + off, g_vl + goff);
    }
    asm volatile("cp.async.commit_group;" ::: "memory");
}

__global__ __launch_bounds__(128) void attn_mma_kernel(const float* __restrict__ mask)
{
    __shared__ __align__(1024) char kvsm[2][16384];
    const int t = threadIdx.x, lane = t & 31, w = t >> 5;   // w in 0..3
    const int g = lane >> 2, tc = lane & 3;
    const int h = blockIdx.y, b = blockIdx.z, bh = b * HH + h;
    const int qb = blockIdx.x * 64;
    const int m0 = qb + w * 16;

    // Q fragments (a0:(g,k0) a1:(g+8,k0) a2:(g,k0+8) a3:(g+8,k0+8)), direct LDG
    uint32_t qh[4][4], ql[4][4];
    {
        const __nv_bfloat16* qhp = g_qh + ((size_t)bh * SS + m0) * DH;
        const __nv_bfloat16* qlp = g_ql + ((size_t)bh * SS + m0) * DH;
        #pragma unroll
        for (int j = 0; j < 4; j++)
            #pragma unroll
            for (int e = 0; e < 4; e++) {
                int r = g + (e & 1) * 8;
                int k = j * 16 + tc * 2 + (e >> 1) * 8;
                qh[j][e] = *(const uint32_t*)(qhp + (size_t)r * DH + k);
                ql[j][e] = *(const uint32_t*)(qlp + (size_t)r * DH + k);
            }
    }

    float ofr[8][4];
    #pragma unroll
    for (int i = 0; i < 8; i++)
        #pragma unroll
        for (int e = 0; e < 4; e++) ofr[i][e] = 0.f;
    float mrow[2] = {-INFINITY, -INFINITY};
    float lrow[2] = {0.f, 0.f};

    const float* maskb = mask + b * SS;
    const float* biash = g_bias + h * BIAS_STRIDE;

    attn_load_kv(t, bh, 0, smem_u32(&kvsm[0][0]));

    const int NT = LKV / 32;   // 65
    for (int kt = 0; kt < NT; kt++) {
        asm volatile("cp.async.wait_group 0;" ::: "memory");
        __syncthreads();
        if (kt + 1 < NT) attn_load_kv(t, bh, kt + 1, smem_u32(&kvsm[(kt + 1) & 1][0]));

        uint32_t kbb = smem_u32(&kvsm[kt & 1][0]);
        uint32_t vbb = kbb + 8192;
        const int kb = kt * 32;

        // ---- scores: S = Qhi Khi^T + Qhi Klo^T + Qlo Khi^T ----
        float sfr[4][4];
        #pragma unroll
        for (int i = 0; i < 4; i++)
            #pragma unroll
            for (int e = 0; e < 4; e++) sfr[i][e] = 0.f;

        #pragma unroll
        for (int j = 0; j < 4; j++) {
            #pragma unroll
            for (int gk2 = 0; gk2 < 2; gk2++) {
                int row = gk2 * 16 + ((lane >> 4) << 3) + (lane & 7);
                int ch  = 2 * j + ((lane >> 3) & 1);
                uint32_t ah = kbb + row * 128 + ((ch ^ (row & 7)) << 4);
                uint32_t kh4[4], kl4[4];
                ldsm_x4(kh4, ah);
                ldsm_x4(kl4, ah + 4096);
                mma16816(sfr[2 * gk2],     qh[j], kh4);
                mma16816(sfr[2 * gk2 + 1], qh[j], kh4 + 2);
                mma16816(sfr[2 * gk2],     qh[j], kl4);
                mma16816(sfr[2 * gk2 + 1], qh[j], kl4 + 2);
                mma16816(sfr[2 * gk2],     ql[j], kh4);
                mma16816(sfr[2 * gk2 + 1], ql[j], kh4 + 2);
            }
        }

        // ---- bias + mask ----
        #pragma unroll
        for (int grp = 0; grp < 4; grp++) {
            int key0 = kb + grp * 8 + tc * 2;
            float mv0 = (key0 >= PFX)     ? maskb[key0 - PFX]     : 0.f;
            float mv1 = (key0 + 1 >= PFX) ? maskb[key0 + 1 - PFX] : 0.f;
            const float* bp = biash + (key0 - (m0 + g) + (BIAS_OFF - PFX));
            sfr[grp][0] += bp[0] + mv0;
            sfr[grp][1] += bp[1] + mv1;
            sfr[grp][2] += bp[-8] + mv0;
            sfr[grp][3] += bp[-7] + mv1;
        }

        // ---- online softmax (rows g and g+8; quad reduce over lanes xor 1,2) ----
        #pragma unroll
        for (int row = 0; row < 2; row++) {
            float mx = sfr[0][row * 2];
            #pragma unroll
            for (int grp = 0; grp < 4; grp++) {
                mx = fmaxf(mx, sfr[grp][row * 2]);
                mx = fmaxf(mx, sfr[grp][row * 2 + 1]);
            }
            mx = fmaxf(mx, __shfl_xor_sync(0xffffffffu, mx, 1));
            mx = fmaxf(mx, __shfl_xor_sync(0xffffffffu, mx, 2));
            float mn = fmaxf(mrow[row], mx);
            float alpha = __expf(mrow[row] - mn);
            mrow[row] = mn;
            float sum = 0.f;
            #pragma unroll
            for (int grp = 0; grp < 4; grp++) {
                float p0 = __expf(sfr[grp][row * 2] - mn);
                float p1 = __expf(sfr[grp][row * 2 + 1] - mn);
                sfr[grp][row * 2] = p0;
                sfr[grp][row * 2 + 1] = p1;
                sum += p0 + p1;
            }
            sum += __shfl_xor_sync(0xffffffffu, sum, 1);
            sum += __shfl_xor_sync(0xffffffffu, sum, 2);
            lrow[row] = lrow[row] * alpha + sum;
            #pragma unroll
            for (int gd = 0; gd < 8; gd++) {
                ofr[gd][row * 2]     *= alpha;
                ofr[gd][row * 2 + 1] *= alpha;
            }
        }

        // ---- P fragments (C-frag is A-frag; split hi/lo) ----
        uint32_t phi[2][4], plo[2][4];
        #pragma unroll
        for (int jk = 0; jk < 2; jk++) {
            #pragma unroll
            for (int e = 0; e < 4; e++) {
                int grp = 2 * jk + (e >> 1);
                int i0  = (e & 1) * 2;
                float p0 = sfr[grp][i0], p1 = sfr[grp][i0 + 1];
                __nv_bfloat16 h0 = __float2bfloat16(p0), h1 = __float2bfloat16(p1);
                phi[jk][e] = pkb2(h0, h1);
                plo[jk][e] = pkb2(__float2bfloat16(p0 - __bfloat162float(h0)),
                                  __float2bfloat16(p1 - __bfloat162float(h1)));
            }
        }

        // ---- PV: O += Phi Vhi + Phi Vlo + Plo Vhi (V via ldmatrix.trans) ----
        #pragma unroll
        for (int jk = 0; jk < 2; jk++) {
            #pragma unroll
            for (int gd2 = 0; gd2 < 4; gd2++) {
                int row = jk * 16 + (((lane >> 3) & 1) << 3) + (lane & 7);
                int ch  = 2 * gd2 + (lane >> 4);
                uint32_t av = vbb + row * 128 + ((ch ^ (row & 7)) << 4);
                uint32_t vh4[4], vl4[4];
                ldsm_x4_t(vh4, av);
                ldsm_x4_t(vl4, av + 4096);
                mma16816(ofr[2 * gd2],     phi[jk], vh4);
                mma16816(ofr[2 * gd2 + 1], phi[jk], vh4 + 2);
                mma16816(ofr[2 * gd2],     phi[jk], vl4);
                mma16816(ofr[2 * gd2 + 1], phi[jk], vl4 + 2);
                mma16816(ofr[2 * gd2],     plo[jk], vh4);
                mma16816(ofr[2 * gd2 + 1], plo[jk], vh4 + 2);
            }
        }
    }

    // ---- epilogue: normalize, split hi/lo, write o3 = [hi|hi|lo] ----
    float inv0 = 1.f / lrow[0], inv1 = 1.f / lrow[1];
    #pragma unroll
    for (int gd = 0; gd < 8; gd++) {
        int d0 = gd * 8 + tc * 2;
        int k  = h * 64 + d0;
        #pragma unroll
        for (int row = 0; row < 2; row++) {
            float v0 = ofr[gd][row * 2]     * (row ? inv1 : inv0);
            float v1 = ofr[gd][row * 2 + 1] * (row ? inv1 : inv0);
            __nv_bfloat16 h0 = __float2bfloat16(v0), h1 = __float2bfloat16(v1);
            uint32_t hi = pkb2(h0, h1);
            uint32_t lo = pkb2(__float2bfloat16(v0 - __bfloat162float(h0)),
                               __float2bfloat16(v1 - __bfloat162float(h1)));
            size_t rbase = ((size_t)(b * SS + m0 + g + row * 8)) * K3 + k;
            *(uint32_t*)(g_o3 + rbase)        = hi;
            *(uint32_t*)(g_o3 + rbase + 1024) = hi;
            *(uint32_t*)(g_o3 + rbase + 2048) = lo;
        }
    }
}

// ---------------- launch ----------------
extern "C" void kernel_launch(void* const* d_in, const int* in_sizes, int n_in,
                              void* d_out, int out_size)
{
    const float* hidden = (const float*)d_in[0];
    const float* mask   = (const float*)d_in[1];
    const float* pk     = (const float*)d_in[2];
    const float* pv     = (const float*)d_in[3];
    const float* Wq     = (const float*)d_in[4];
    const float* Wk     = (const float*)d_in[5];
    const float* Wv     = (const float*)d_in[6];
    const float* Wo     = (const float*)d_in[7];
    const float* rel    = (const float*)d_in[8];
    float* out = (float*)d_out;

    bias_init_kernel<<<(HH * 4127 + 255) / 256, 256>>>(rel);
    prefix_copy_kernel<<<(BB * HH * PFX * DH + 255) / 256, 256>>>(pk, pv);
    split_hidden_kernel<<<(BB * SS * DDIM + 255) / 256, 256>>>(hidden);
    split_w_kernel<<<dim3(32, 32, 4), 256>>>(Wq, Wk, Wv, Wo);
    gemm_qkv_mma<<<dim3(8, 32, 3), 256>>>();
    attn_mma_kernel<<<dim3(SS / 64, HH, BB), 128>>>(mask);
    gemm_o_mma<<<dim3(8, 32), 256>>>(out);
}

// round 7
// speedup vs baseline: 2.5528x; 1.0853x over previous
#include <cuda_runtime.h>
#include <cuda_bf16.h>
#include <math.h>
#include <stdint.h>

// Problem constants
#define BB   2
#define HH   16
#define SS   2048
#define DDIM 1024
#define DH   64
#define PFX  32
#define LKV  2080          // PFX + SS = 65 * 32
#define K3   3072          // 3x split-concatenated K
#define BIAS_STRIDE 4160
#define BIAS_OFF 2079

// ---------------- scratch (static device globals; no allocation) ----------------
__device__ float g_bias[HH * BIAS_STRIDE];                  // [h][rel+2079]
__device__ __nv_bfloat16 g_a3[(size_t)BB * SS * K3];        // hidden split [m][k3]
__device__ __nv_bfloat16 g_w3[(size_t)4 * DDIM * K3];       // Wq,Wk,Wv,Wo split+T [n][k3]
__device__ __nv_bfloat16 g_o3[(size_t)BB * SS * K3];        // attn-out split [m][k3]
__device__ __nv_bfloat16 g_qh[(size_t)BB * HH * SS * DH];   // [bh][s][d]
__device__ __nv_bfloat16 g_ql[(size_t)BB * HH * SS * DH];
__device__ __nv_bfloat16 g_kh[(size_t)BB * HH * LKV * DH];  // [bh][key][d]
__device__ __nv_bfloat16 g_kl[(size_t)BB * HH * LKV * DH];
__device__ __nv_bfloat16 g_vh[(size_t)BB * HH * LKV * DH];
__device__ __nv_bfloat16 g_vl[(size_t)BB * HH * LKV * DH];

// ======================= PTX helpers (sm_80-class only) =======================
__device__ __forceinline__ uint32_t smem_u32(const void* p) {
    uint32_t a;
    asm("{ .reg .u64 t; cvta.to.shared.u64 t, %1; cvt.u32.u64 %0, t; }" : "=r"(a) : "l"(p));
    return a;
}
__device__ __forceinline__ void cpa16(uint32_t dst, const void* src) {
    asm volatile("cp.async.cg.shared.global [%0], [%1], 16;" :: "r"(dst), "l"(src));
}
__device__ __forceinline__ void ldsm_x4(uint32_t* r, uint32_t addr) {
    asm volatile("ldmatrix.sync.aligned.m8n8.x4.shared.b16 {%0,%1,%2,%3}, [%4];"
                 : "=r"(r[0]), "=r"(r[1]), "=r"(r[2]), "=r"(r[3]) : "r"(addr));
}
__device__ __forceinline__ void ldsm_x4_t(uint32_t* r, uint32_t addr) {
    asm volatile("ldmatrix.sync.aligned.m8n8.x4.trans.shared.b16 {%0,%1,%2,%3}, [%4];"
                 : "=r"(r[0]), "=r"(r[1]), "=r"(r[2]), "=r"(r[3]) : "r"(addr));
}
__device__ __forceinline__ void mma16816(float* d, const uint32_t* a, const uint32_t* b) {
    asm volatile("mma.sync.aligned.m16n8k16.row.col.f32.bf16.bf16.f32 "
                 "{%0,%1,%2,%3}, {%4,%5,%6,%7}, {%8,%9}, {%0,%1,%2,%3};"
                 : "+f"(d[0]), "+f"(d[1]), "+f"(d[2]), "+f"(d[3])
                 : "r"(a[0]), "r"(a[1]), "r"(a[2]), "r"(a[3]), "r"(b[0]), "r"(b[1]));
}
__device__ __forceinline__ uint32_t pkb2(__nv_bfloat16 a, __nv_bfloat16 b) {
    uint16_t ua = *(uint16_t*)&a, ub = *(uint16_t*)&b;
    return (uint32_t)ua | ((uint32_t)ub << 16);
}
// GEMM smem swizzle: rows of 64B (32 bf16), quad = 16B unit
__device__ __forceinline__ uint32_t sw_addr(uint32_t base, int r, int k) {
    int quad = k >> 3;
    int sw   = quad ^ ((r >> 1) & 3);
    return base + r * 64 + sw * 16 + (k & 7) * 2;
}

// ---------------- bias table init ----------------
__global__ void bias_init_kernel(const float* __restrict__ rel_table)
{
    int idx = blockIdx.x * blockDim.x + threadIdx.x;
    const int total = HH * 4127;
    if (idx >= total) return;
    int h   = idx / 4127;
    int r   = idx - h * 4127;
    int rel = r - BIAS_OFF;

    int ret = (rel > 0) ? 16 : 0;
    int n   = rel < 0 ? -rel : rel;
    int bkt;
    if (n < 8) {
        bkt = n;
    } else {
        float nf = (float)n;
        int vl = 8 + (int)(logf(nf * 0.125f) / 2.772588722239781f * 8.0f);
        bkt = vl < 15 ? vl : 15;
    }
    bkt += ret;
    g_bias[h * BIAS_STRIDE + r] = rel_table[bkt * HH + h];
}

// ---------------- prefix K/V copy (fp32 -> bf16 hi/lo) ----------------
__global__ void prefix_copy_kernel(const float* __restrict__ pk,
                                   const float* __restrict__ pv)
{
    int idx = blockIdx.x * blockDim.x + threadIdx.x;
    const int total = BB * HH * PFX * DH;
    if (idx >= total) return;
    int d  = idx & 63;
    int p  = (idx >> 6) & 31;
    int bh = idx >> 11;
    size_t o = ((size_t)bh * LKV + p) * DH + d;
    float kx = pk[idx], vx = pv[idx];
    __nv_bfloat16 khf = __float2bfloat16(kx);
    __nv_bfloat16 vhf = __float2bfloat16(vx);
    g_kh[o] = khf;
    g_kl[o] = __float2bfloat16(kx - __bfloat162float(khf));
    g_vh[o] = vhf;
    g_vl[o] = __float2bfloat16(vx - __bfloat162float(vhf));
}

// ---------------- split kernels (bf16 hi/lo, 3x concat along K) ----------------
// vectorized: 4 floats -> 2 packed uint32 (hi) + 2 packed uint32 (lo)
__global__ void split_hidden_kernel(const float* __restrict__ src)
{
    int i4 = blockIdx.x * blockDim.x + threadIdx.x;    // index in float4 units
    const int n4 = (BB * SS * DDIM) / 4;
    if (i4 >= n4) return;
    float4 x = *(const float4*)(src + (size_t)i4 * 4);
    __nv_bfloat16 h0 = __float2bfloat16(x.x), h1 = __float2bfloat16(x.y);
    __nv_bfloat16 h2 = __float2bfloat16(x.z), h3 = __float2bfloat16(x.w);
    uint32_t hiA = pkb2(h0, h1), hiB = pkb2(h2, h3);
    uint32_t loA = pkb2(__float2bfloat16(x.x - __bfloat162float(h0)),
                        __float2bfloat16(x.y - __bfloat162float(h1)));
    uint32_t loB = pkb2(__float2bfloat16(x.z - __bfloat162float(h2)),
                        __float2bfloat16(x.w - __bfloat162float(h3)));
    int i = i4 * 4;
    size_t b = (size_t)(i >> 10) * K3 + (i & 1023);
    uint32_t* p0 = (uint32_t*)(g_a3 + b);
    p0[0] = hiA; p0[1] = hiB;
    uint32_t* p1 = (uint32_t*)(g_a3 + b + 1024);
    p1[0] = hiA; p1[1] = hiB;
    uint32_t* p2 = (uint32_t*)(g_a3 + b + 2048);
    p2[0] = loA; p2[1] = loB;
}

// W [k][n] fp32 -> W3 [n][k3] bf16 = [hi | lo | hi] (transposed)
__global__ __launch_bounds__(256) void split_w_kernel(const float* __restrict__ Wq,
                                                      const float* __restrict__ Wk,
                                                      const float* __restrict__ Wv,
                                                      const float* __restrict__ Wo)
{
    __shared__ float tile[32][33];
    const int z = blockIdx.z;
    const float* W = (z == 0) ? Wq : (z == 1) ? Wk : (z == 2) ? Wv : Wo;
    __nv_bfloat16* dst = g_w3 + (size_t)z * DDIM * K3;

    const int n0 = blockIdx.x * 32, k0 = blockIdx.y * 32;
    const int tx = threadIdx.x & 31, ty0 = threadIdx.x >> 5;
    #pragma unroll
    for (int r = 0; r < 4; r++) {
        int ty = ty0 + r * 8;
        tile[ty][tx] = W[(size_t)(k0 + ty) * DDIM + n0 + tx];
    }
    __syncthreads();
    #pragma unroll
    for (int r = 0; r < 4; r++) {
        int ty = ty0 + r * 8;
        float x = tile[tx][ty];
        __nv_bfloat16 h = __float2bfloat16(x);
        __nv_bfloat16 l = __float2bfloat16(x - __bfloat162float(h));
        size_t b = (size_t)(n0 + ty) * K3 + (k0 + tx);
        dst[b]        = h;
        dst[b + 1024] = l;
        dst[b + 2048] = h;
    }
}

// ---------------- mma.sync bf16 GEMM: C[4096 x 1024] = A3 * W3^T ----------------
#define CHUNK 32
#define NSTG 3
#define STG_BYTES 16384

__device__ __forceinline__ void gemm_load_chunk(uint32_t sb,
        const __nv_bfloat16* __restrict__ Ag, const __nv_bfloat16* __restrict__ Bg,
        int mblock, int nblock, int c)
{
    const int t = threadIdx.x;
    const int st = c % NSTG;
    uint32_t ab = sb + st * STG_BYTES;
    uint32_t bb = ab + 8192;
    #pragma unroll
    for (int i = 0; i < 2; i++) {
        int idx = t + i * 256;
        int r = idx >> 2, q = idx & 3;
        uint32_t soff = (uint32_t)(r * 64 + ((q ^ ((r >> 1) & 3)) << 4));
        const char* as = (const char*)(Ag + (size_t)(mblock + r) * K3 + c * CHUNK + q * 8);
        const char* bs = (const char*)(Bg + (size_t)(nblock + r) * K3 + c * CHUNK + q * 8);
        cpa16(ab + soff, as);
        cpa16(bb + soff, bs);
    }
    asm volatile("cp.async.commit_group;" ::: "memory");
}

__device__ __forceinline__ void gemm_mma_body(const __nv_bfloat16* __restrict__ Ag,
                                              const __nv_bfloat16* __restrict__ Bg,
                                              int mblock, int nblock, int flavor,
                                              float* __restrict__ outp)
{
    __shared__ __align__(128) char smbuf[NSTG * STG_BYTES];
    uint32_t sb = smem_u32(smbuf);
    const int t    = threadIdx.x;
    const int lane = t & 31;
    const int w    = t >> 5;
    const int wm   = w >> 1;
    const int wn   = w & 1;

    float acc[2][8][4];
    #pragma unroll
    for (int f = 0; f < 2; f++)
        #pragma unroll
        for (int p = 0; p < 8; p++)
            #pragma unroll
            for (int e = 0; e < 4; e++) acc[f][p][e] = 0.f;

    const int NCH = K3 / CHUNK;   // 96

    gemm_load_chunk(sb, Ag, Bg, mblock, nblock, 0);
    gemm_load_chunk(sb, Ag, Bg, mblock, nblock, 1);

    for (int c = 0; c < NCH; c++) {
        if (c < NCH - 1) asm volatile("cp.async.wait_group 1;" ::: "memory");
        else             asm volatile("cp.async.wait_group 0;" ::: "memory");
        __syncthreads();
        // single sync per iter: all warps have finished reading stage (c-1)%NSTG
        // (== (c+2)%NSTG) during iter c-1, so the load below is safe and
        // overlaps with this iteration's MMA work.
        if (c + 2 < NCH) gemm_load_chunk(sb, Ag, Bg, mblock, nblock, c + 2);

        uint32_t ab = sb + (c % NSTG) * STG_BYTES;
        uint32_t bb = ab + 8192;

        #pragma unroll
        for (int ks = 0; ks < 2; ks++) {
            uint32_t afr[2][4];
            #pragma unroll
            for (int f = 0; f < 2; f++) {
                int r = wm * 32 + f * 16 + (lane & 15);
                int k = ks * 16 + (lane >> 4) * 8;
                ldsm_x4(afr[f], sw_addr(ab, r, k));
            }
            uint32_t bfr[8][2];
            #pragma unroll
            for (int p = 0; p < 4; p++) {
                int n = wn * 64 + p * 16 + ((lane >> 4) & 1) * 8 + (lane & 7);
                int k = ks * 16 + ((lane >> 3) & 1) * 8;
                uint32_t r4[4];
                ldsm_x4(r4, sw_addr(bb, n, k));
                bfr[p * 2][0]     = r4[0];
                bfr[p * 2][1]     = r4[1];
                bfr[p * 2 + 1][0] = r4[2];
                bfr[p * 2 + 1][1] = r4[3];
            }
            #pragma unroll
            for (int f = 0; f < 2; f++)
                #pragma unroll
                for (int p = 0; p < 8; p++)
                    mma16816(acc[f][p], afr[f], bfr[p]);
        }
    }

    // epilogue: m = .. + (lane>>2) + e2*8 ; n pair = .. + (lane&3)*2 + {0,1}
    #pragma unroll
    for (int f = 0; f < 2; f++) {
        #pragma unroll
        for (int p = 0; p < 8; p++) {
            #pragma unroll
            for (int e2 = 0; e2 < 2; e2++) {
                int m  = mblock + wm * 32 + f * 16 + (lane >> 2) + e2 * 8;
                int n0 = nblock + wn * 64 + p * 8 + ((lane & 3) << 1);
                float v0 = acc[f][p][e2 * 2], v1 = acc[f][p][e2 * 2 + 1];
                if (flavor == 3) {
                    outp[(size_t)m * DDIM + n0]     = v0;
                    outp[(size_t)m * DDIM + n0 + 1] = v1;
                } else {
                    __nv_bfloat16 h0 = __float2bfloat16(v0), h1 = __float2bfloat16(v1);
                    uint32_t hi = pkb2(h0, h1);
                    uint32_t lo = pkb2(__float2bfloat16(v0 - __bfloat162float(h0)),
                                       __float2bfloat16(v1 - __bfloat162float(h1)));
                    int b0 = m >> 11, s = m & 2047, hh = n0 >> 6, d = n0 & 63;
                    int bh = b0 * HH + hh;
                    if (flavor == 0) {
                        size_t o = ((size_t)bh * SS + s) * DH + d;
                        *(uint32_t*)(g_qh + o) = hi;
                        *(uint32_t*)(g_ql + o) = lo;
                    } else {
                        size_t o = ((size_t)bh * LKV + PFX + s) * DH + d;
                        if (flavor == 1) {
                            *(uint32_t*)(g_kh + o) = hi;
                            *(uint32_t*)(g_kl + o) = lo;
                        } else {
                            *(uint32_t*)(g_vh + o) = hi;
                            *(uint32_t*)(g_vl + o) = lo;
                        }
                    }
                }
            }
        }
    }
}

__global__ __launch_bounds__(256, 2) void gemm_qkv_mma()
{
    const int z = blockIdx.z;
    gemm_mma_body(g_a3, g_w3 + (size_t)z * DDIM * K3,
                  blockIdx.y * 128, blockIdx.x * 128, z, nullptr);
}

__global__ __launch_bounds__(256, 2) void gemm_o_mma(float* __restrict__ out)
{
    gemm_mma_body(g_o3, g_w3 + (size_t)3 * DDIM * K3,
                  blockIdx.y * 128, blockIdx.x * 128, 3, out);
}

// ---------------- mma.sync flash attention ----------------
// 128 thr / 4 warps; Q-tile 64 (warp = 16 rows); KV-tile 32; 2-stage cp.async.
// smem 32KB, forced 3 CTAs/SM for latency hiding.
// Stage layout: Khi(4K) Klo(4K) Vhi(4K) Vlo(4K) = 16KB; rows of 128B, chunk^=(row&7).
__device__ __forceinline__ void attn_load_kv(int t, int bh, int kt, uint32_t base)
{
    #pragma unroll
    for (int i = 0; i < 2; i++) {
        const int row = (t >> 3) + i * 16;
        const int c = t & 7;
        uint32_t off = (uint32_t)(row * 128 + ((c ^ (row & 7)) << 4));
        size_t goff = ((size_t)bh * LKV + kt * 32 + row) * DH + c * 8;
        cpa16(base + off,         g_kh + goff);
        cpa16(base + 4096 + off,  g_kl + goff);
        cpa16(base + 8192 + off,  g_vh + goff);
        cpa16(base + 12288 + off, g_vl + goff);
    }
    asm volatile("cp.async.commit_group;" ::: "memory");
}

__global__ __launch_bounds__(128, 3) void attn_mma_kernel(const float* __restrict__ mask)
{
    __shared__ __align__(1024) char kvsm[2][16384];
    const int t = threadIdx.x, lane = t & 31, w = t >> 5;   // w in 0..3
    const int g = lane >> 2, tc = lane & 3;
    const int h = blockIdx.y, b = blockIdx.z, bh = b * HH + h;
    const int qb = blockIdx.x * 64;
    const int m0 = qb + w * 16;

    // Q fragments (a0:(g,k0) a1:(g+8,k0) a2:(g,k0+8) a3:(g+8,k0+8)), direct LDG
    uint32_t qh[4][4], ql[4][4];
    {
        const __nv_bfloat16* qhp = g_qh + ((size_t)bh * SS + m0) * DH;
        const __nv_bfloat16* qlp = g_ql + ((size_t)bh * SS + m0) * DH;
        #pragma unroll
        for (int j = 0; j < 4; j++)
            #pragma unroll
            for (int e = 0; e < 4; e++) {
                int r = g + (e & 1) * 8;
                int k = j * 16 + tc * 2 + (e >> 1) * 8;
                qh[j][e] = *(const uint32_t*)(qhp + (size_t)r * DH + k);
                ql[j][e] = *(const uint32_t*)(qlp + (size_t)r * DH + k);
            }
    }

    float ofr[8][4];
    #pragma unroll
    for (int i = 0; i < 8; i++)
        #pragma unroll
        for (int e = 0; e < 4; e++) ofr[i][e] = 0.f;
    float mrow[2] = {-INFINITY, -INFINITY};
    float lrow[2] = {0.f, 0.f};

    const float* maskb = mask + b * SS;
    const float* biash = g_bias + h * BIAS_STRIDE;

    attn_load_kv(t, bh, 0, smem_u32(&kvsm[0][0]));

    const int NT = LKV / 32;   // 65
    for (int kt = 0; kt < NT; kt++) {
        asm volatile("cp.async.wait_group 0;" ::: "memory");
        __syncthreads();
        if (kt + 1 < NT) attn_load_kv(t, bh, kt + 1, smem_u32(&kvsm[(kt + 1) & 1][0]));

        uint32_t kbb = smem_u32(&kvsm[kt & 1][0]);
        uint32_t vbb = kbb + 8192;
        const int kb = kt * 32;

        // ---- scores: S = Qhi Khi^T + Qhi Klo^T + Qlo Khi^T ----
        float sfr[4][4];
        #pragma unroll
        for (int i = 0; i < 4; i++)
            #pragma unroll
            for (int e = 0; e < 4; e++) sfr[i][e] = 0.f;

        #pragma unroll
        for (int j = 0; j < 4; j++) {
            #pragma unroll
            for (int gk2 = 0; gk2 < 2; gk2++) {
                int row = gk2 * 16 + ((lane >> 4) << 3) + (lane & 7);
                int ch  = 2 * j + ((lane >> 3) & 1);
                uint32_t ah = kbb + row * 128 + ((ch ^ (row & 7)) << 4);
                uint32_t kh4[4], kl4[4];
                ldsm_x4(kh4, ah);
                ldsm_x4(kl4, ah + 4096);
                mma16816(sfr[2 * gk2],     qh[j], kh4);
                mma16816(sfr[2 * gk2 + 1], qh[j], kh4 + 2);
                mma16816(sfr[2 * gk2],     qh[j], kl4);
                mma16816(sfr[2 * gk2 + 1], qh[j], kl4 + 2);
                mma16816(sfr[2 * gk2],     ql[j], kh4);
                mma16816(sfr[2 * gk2 + 1], ql[j], kh4 + 2);
            }
        }

        // ---- bias + mask ----
        #pragma unroll
        for (int grp = 0; grp < 4; grp++) {
            int key0 = kb + grp * 8 + tc * 2;
            float mv0 = (key0 >= PFX)     ? maskb[key0 - PFX]     : 0.f;
            float mv1 = (key0 + 1 >= PFX) ? maskb[key0 + 1 - PFX] : 0.f;
            const float* bp = biash + (key0 - (m0 + g) + (BIAS_OFF - PFX));
            sfr[grp][0] += bp[0] + mv0;
            sfr[grp][1] += bp[1] + mv1;
            sfr[grp][2] += bp[-8] + mv0;
            sfr[grp][3] += bp[-7] + mv1;
        }

        // ---- online softmax (rows g and g+8; quad reduce over lanes xor 1,2) ----
        #pragma unroll
        for (int row = 0; row < 2; row++) {
            float mx = sfr[0][row * 2];
            #pragma unroll
            for (int grp = 0; grp < 4; grp++) {
                mx = fmaxf(mx, sfr[grp][row * 2]);
                mx = fmaxf(mx, sfr[grp][row * 2 + 1]);
            }
            mx = fmaxf(mx, __shfl_xor_sync(0xffffffffu, mx, 1));
            mx = fmaxf(mx, __shfl_xor_sync(0xffffffffu, mx, 2));
            float mn = fmaxf(mrow[row], mx);
            float alpha = __expf(mrow[row] - mn);
            mrow[row] = mn;
            float sum = 0.f;
            #pragma unroll
            for (int grp = 0; grp < 4; grp++) {
                float p0 = __expf(sfr[grp][row * 2] - mn);
                float p1 = __expf(sfr[grp][row * 2 + 1] - mn);
                sfr[grp][row * 2] = p0;
                sfr[grp][row * 2 + 1] = p1;
                sum += p0 + p1;
            }
            sum += __shfl_xor_sync(0xffffffffu, sum, 1);
            sum += __shfl_xor_sync(0xffffffffu, sum, 2);
            lrow[row] = lrow[row] * alpha + sum;
            #pragma unroll
            for (int gd = 0; gd < 8; gd++) {
                ofr[gd][row * 2]     *= alpha;
                ofr[gd][row * 2 + 1] *= alpha;
            }
        }

        // ---- P fragments (C-frag is A-frag; split hi/lo) ----
        uint32_t phi[2][4], plo[2][4];
        #pragma unroll
        for (int jk = 0; jk < 2; jk++) {
            #pragma unroll
            for (int e = 0; e < 4; e++) {
                int grp = 2 * jk + (e >> 1);
                int i0  = (e & 1) * 2;
                float p0 = sfr[grp][i0], p1 = sfr[grp][i0 + 1];
                __nv_bfloat16 h0 = __float2bfloat16(p0), h1 = __float2bfloat16(p1);
                phi[jk][e] = pkb2(h0, h1);
                plo[jk][e] = pkb2(__float2bfloat16(p0 - __bfloat162float(h0)),
                                  __float2bfloat16(p1 - __bfloat162float(h1)));
            }
        }

        // ---- PV: O += Phi Vhi + Phi Vlo + Plo Vhi (V via ldmatrix.trans) ----
        #pragma unroll
        for (int jk = 0; jk < 2; jk++) {
            #pragma unroll
            for (int gd2 = 0; gd2 < 4; gd2++) {
                int row = jk * 16 + (((lane >> 3) & 1) << 3) + (lane & 7);
                int ch  = 2 * gd2 + (lane >> 4);
                uint32_t av = vbb + row * 128 + ((ch ^ (row & 7)) << 4);
                uint32_t vh4[4], vl4[4];
                ldsm_x4_t(vh4, av);
                ldsm_x4_t(vl4, av + 4096);
                mma16816(ofr[2 * gd2],     phi[jk], vh4);
                mma16816(ofr[2 * gd2 + 1], phi[jk], vh4 + 2);
                mma16816(ofr[2 * gd2],     phi[jk], vl4);
                mma16816(ofr[2 * gd2 + 1], phi[jk], vl4 + 2);
                mma16816(ofr[2 * gd2],     plo[jk], vh4);
                mma16816(ofr[2 * gd2 + 1], plo[jk], vh4 + 2);
            }
        }
    }

    // ---- epilogue: normalize, split hi/lo, write o3 = [hi|hi|lo] ----
    float inv0 = 1.f / lrow[0], inv1 = 1.f / lrow[1];
    #pragma unroll
    for (int gd = 0; gd < 8; gd++) {
        int d0 = gd * 8 + tc * 2;
        int k  = h * 64 + d0;
        #pragma unroll
        for (int row = 0; row < 2; row++) {
            float v0 = ofr[gd][row * 2]     * (row ? inv1 : inv0);
            float v1 = ofr[gd][row * 2 + 1] * (row ? inv1 : inv0);
            __nv_bfloat16 h0 = __float2bfloat16(v0), h1 = __float2bfloat16(v1);
            uint32_t hi = pkb2(h0, h1);
            uint32_t lo = pkb2(__float2bfloat16(v0 - __bfloat162float(h0)),
                               __float2bfloat16(v1 - __bfloat162float(h1)));
            size_t rbase = ((size_t)(b * SS + m0 + g + row * 8)) * K3 + k;
            *(uint32_t*)(g_o3 + rbase)        = hi;
            *(uint32_t*)(g_o3 + rbase + 1024) = hi;
            *(uint32_t*)(g_o3 + rbase + 2048) = lo;
        }
    }
}

// ---------------- launch ----------------
extern "C" void kernel_launch(void* const* d_in, const int* in_sizes, int n_in,
                              void* d_out, int out_size)
{
    const float* hidden = (const float*)d_in[0];
    const float* mask   = (const float*)d_in[1];
    const float* pk     = (const float*)d_in[2];
    const float* pv     = (const float*)d_in[3];
    const float* Wq     = (const float*)d_in[4];
    const float* Wk     = (const float*)d_in[5];
    const float* Wv     = (const float*)d_in[6];
    const float* Wo     = (const float*)d_in[7];
    const float* rel    = (const float*)d_in[8];
    float* out = (float*)d_out;

    bias_init_kernel<<<(HH * 4127 + 255) / 256, 256>>>(rel);
    prefix_copy_kernel<<<(BB * HH * PFX * DH + 255) / 256, 256>>>(pk, pv);
    split_hidden_kernel<<<(BB * SS * DDIM / 4 + 255) / 256, 256>>>(hidden);
    split_w_kernel<<<dim3(32, 32, 4), 256>>>(Wq, Wk, Wv, Wo);
    gemm_qkv_mma<<<dim3(8, 32, 3), 256>>>();
    attn_mma_kernel<<<dim3(SS / 64, HH, BB), 128>>>(mask);
    gemm_o_mma<<<dim3(8, 32), 256>>>(out);
}

// round 8
// speedup vs baseline: 2.6354x; 1.0324x over previous
#include <cuda_runtime.h>
#include <cuda_bf16.h>
#include <math.h>
#include <stdint.h>

// Problem constants
#define BB   2
#define HH   16
#define SS   2048
#define DDIM 1024
#define DH   64
#define PFX  32
#define LKV  2080          // PFX + SS = 65 * 32
#define K3   3072          // 3x split-concatenated K
#define BIAS_STRIDE 4160
#define BIAS_OFF 2079

// ---------------- scratch (static device globals; no allocation) ----------------
__device__ float g_bias[HH * BIAS_STRIDE];                  // [h][rel+2079]
__device__ __nv_bfloat16 g_a3[(size_t)BB * SS * K3];        // hidden split [m][k3]
__device__ __nv_bfloat16 g_w3[(size_t)4 * DDIM * K3];       // Wq,Wk,Wv,Wo split+T [n][k3]
__device__ __nv_bfloat16 g_o3[(size_t)BB * SS * K3];        // attn-out split [m][k3]
__device__ __nv_bfloat16 g_qh[(size_t)BB * HH * SS * DH];   // [bh][s][d]
__device__ __nv_bfloat16 g_ql[(size_t)BB * HH * SS * DH];
__device__ __nv_bfloat16 g_kh[(size_t)BB * HH * LKV * DH];  // [bh][key][d]
__device__ __nv_bfloat16 g_kl[(size_t)BB * HH * LKV * DH];
__device__ __nv_bfloat16 g_vh[(size_t)BB * HH * LKV * DH];
__device__ __nv_bfloat16 g_vl[(size_t)BB * HH * LKV * DH];

// ======================= PTX helpers (sm_80-class only) =======================
__device__ __forceinline__ uint32_t smem_u32(const void* p) {
    uint32_t a;
    asm("{ .reg .u64 t; cvta.to.shared.u64 t, %1; cvt.u32.u64 %0, t; }" : "=r"(a) : "l"(p));
    return a;
}
__device__ __forceinline__ void cpa16(uint32_t dst, const void* src) {
    asm volatile("cp.async.cg.shared.global [%0], [%1], 16;" :: "r"(dst), "l"(src));
}
__device__ __forceinline__ void ldsm_x4(uint32_t* r, uint32_t addr) {
    asm volatile("ldmatrix.sync.aligned.m8n8.x4.shared.b16 {%0,%1,%2,%3}, [%4];"
                 : "=r"(r[0]), "=r"(r[1]), "=r"(r[2]), "=r"(r[3]) : "r"(addr));
}
__device__ __forceinline__ void ldsm_x4_t(uint32_t* r, uint32_t addr) {
    asm volatile("ldmatrix.sync.aligned.m8n8.x4.trans.shared.b16 {%0,%1,%2,%3}, [%4];"
                 : "=r"(r[0]), "=r"(r[1]), "=r"(r[2]), "=r"(r[3]) : "r"(addr));
}
__device__ __forceinline__ void mma16816(float* d, const uint32_t* a, const uint32_t* b) {
    asm volatile("mma.sync.aligned.m16n8k16.row.col.f32.bf16.bf16.f32 "
                 "{%0,%1,%2,%3}, {%4,%5,%6,%7}, {%8,%9}, {%0,%1,%2,%3};"
                 : "+f"(d[0]), "+f"(d[1]), "+f"(d[2]), "+f"(d[3])
                 : "r"(a[0]), "r"(a[1]), "r"(a[2]), "r"(a[3]), "r"(b[0]), "r"(b[1]));
}
__device__ __forceinline__ uint32_t pkb2(__nv_bfloat16 a, __nv_bfloat16 b) {
    uint16_t ua = *(uint16_t*)&a, ub = *(uint16_t*)&b;
    return (uint32_t)ua | ((uint32_t)ub << 16);
}
// GEMM smem swizzle: rows of 64B (32 bf16), quad = 16B unit
__device__ __forceinline__ uint32_t sw_addr(uint32_t base, int r, int k) {
    int quad = k >> 3;
    int sw   = quad ^ ((r >> 1) & 3);
    return base + r * 64 + sw * 16 + (k & 7) * 2;
}
#define CP_COMMIT() asm volatile("cp.async.commit_group;" ::: "memory")

// ---------------- bias table init ----------------
__global__ void bias_init_kernel(const float* __restrict__ rel_table)
{
    int idx = blockIdx.x * blockDim.x + threadIdx.x;
    const int total = HH * 4127;
    if (idx >= total) return;
    int h   = idx / 4127;
    int r   = idx - h * 4127;
    int rel = r - BIAS_OFF;

    int ret = (rel > 0) ? 16 : 0;
    int n   = rel < 0 ? -rel : rel;
    int bkt;
    if (n < 8) {
        bkt = n;
    } else {
        float nf = (float)n;
        int vl = 8 + (int)(logf(nf * 0.125f) / 2.772588722239781f * 8.0f);
        bkt = vl < 15 ? vl : 15;
    }
    bkt += ret;
    g_bias[h * BIAS_STRIDE + r] = rel_table[bkt * HH + h];
}

// ---------------- prefix K/V copy (fp32 -> bf16 hi/lo) ----------------
__global__ void prefix_copy_kernel(const float* __restrict__ pk,
                                   const float* __restrict__ pv)
{
    int idx = blockIdx.x * blockDim.x + threadIdx.x;
    const int total = BB * HH * PFX * DH;
    if (idx >= total) return;
    int d  = idx & 63;
    int p  = (idx >> 6) & 31;
    int bh = idx >> 11;
    size_t o = ((size_t)bh * LKV + p) * DH + d;
    float kx = pk[idx], vx = pv[idx];
    __nv_bfloat16 khf = __float2bfloat16(kx);
    __nv_bfloat16 vhf = __float2bfloat16(vx);
    g_kh[o] = khf;
    g_kl[o] = __float2bfloat16(kx - __bfloat162float(khf));
    g_vh[o] = vhf;
    g_vl[o] = __float2bfloat16(vx - __bfloat162float(vhf));
}

// ---------------- split kernels (bf16 hi/lo, 3x concat along K) ----------------
__global__ void split_hidden_kernel(const float* __restrict__ src)
{
    int i4 = blockIdx.x * blockDim.x + threadIdx.x;
    const int n4 = (BB * SS * DDIM) / 4;
    if (i4 >= n4) return;
    float4 x = *(const float4*)(src + (size_t)i4 * 4);
    __nv_bfloat16 h0 = __float2bfloat16(x.x), h1 = __float2bfloat16(x.y);
    __nv_bfloat16 h2 = __float2bfloat16(x.z), h3 = __float2bfloat16(x.w);
    uint32_t hiA = pkb2(h0, h1), hiB = pkb2(h2, h3);
    uint32_t loA = pkb2(__float2bfloat16(x.x - __bfloat162float(h0)),
                        __float2bfloat16(x.y - __bfloat162float(h1)));
    uint32_t loB = pkb2(__float2bfloat16(x.z - __bfloat162float(h2)),
                        __float2bfloat16(x.w - __bfloat162float(h3)));
    int i = i4 * 4;
    size_t b = (size_t)(i >> 10) * K3 + (i & 1023);
    uint32_t* p0 = (uint32_t*)(g_a3 + b);
    p0[0] = hiA; p0[1] = hiB;
    uint32_t* p1 = (uint32_t*)(g_a3 + b + 1024);
    p1[0] = hiA; p1[1] = hiB;
    uint32_t* p2 = (uint32_t*)(g_a3 + b + 2048);
    p2[0] = loA; p2[1] = loB;
}

// W [k][n] fp32 -> W3 [n][k3] bf16 = [hi | lo | hi] (transposed)
__global__ __launch_bounds__(256) void split_w_kernel(const float* __restrict__ Wq,
                                                      const float* __restrict__ Wk,
                                                      const float* __restrict__ Wv,
                                                      const float* __restrict__ Wo)
{
    __shared__ float tile[32][33];
    const int z = blockIdx.z;
    const float* W = (z == 0) ? Wq : (z == 1) ? Wk : (z == 2) ? Wv : Wo;
    __nv_bfloat16* dst = g_w3 + (size_t)z * DDIM * K3;

    const int n0 = blockIdx.x * 32, k0 = blockIdx.y * 32;
    const int tx = threadIdx.x & 31, ty0 = threadIdx.x >> 5;
    #pragma unroll
    for (int r = 0; r < 4; r++) {
        int ty = ty0 + r * 8;
        tile[ty][tx] = W[(size_t)(k0 + ty) * DDIM + n0 + tx];
    }
    __syncthreads();
    #pragma unroll
    for (int r = 0; r < 4; r++) {
        int ty = ty0 + r * 8;
        float x = tile[tx][ty];
        __nv_bfloat16 h = __float2bfloat16(x);
        __nv_bfloat16 l = __float2bfloat16(x - __bfloat162float(h));
        size_t b = (size_t)(n0 + ty) * K3 + (k0 + tx);
        dst[b]        = h;
        dst[b + 1024] = l;
        dst[b + 2048] = h;
    }
}

// ---------------- mma.sync bf16 GEMM: C[4096 x 1024] = A3 * W3^T ----------------
#define CHUNK 32
#define NSTG 3
#define STG_BYTES 16384

__device__ __forceinline__ void gemm_load_chunk(uint32_t sb,
        const __nv_bfloat16* __restrict__ Ag, const __nv_bfloat16* __restrict__ Bg,
        int mblock, int nblock, int c)
{
    const int t = threadIdx.x;
    const int st = c % NSTG;
    uint32_t ab = sb + st * STG_BYTES;
    uint32_t bb = ab + 8192;
    #pragma unroll
    for (int i = 0; i < 2; i++) {
        int idx = t + i * 256;
        int r = idx >> 2, q = idx & 3;
        uint32_t soff = (uint32_t)(r * 64 + ((q ^ ((r >> 1) & 3)) << 4));
        const char* as = (const char*)(Ag + (size_t)(mblock + r) * K3 + c * CHUNK + q * 8);
        const char* bs = (const char*)(Bg + (size_t)(nblock + r) * K3 + c * CHUNK + q * 8);
        cpa16(ab + soff, as);
        cpa16(bb + soff, bs);
    }
    CP_COMMIT();
}

__device__ __forceinline__ void gemm_mma_body(const __nv_bfloat16* __restrict__ Ag,
                                              const __nv_bfloat16* __restrict__ Bg,
                                              int mblock, int nblock, int flavor,
                                              float* __restrict__ outp)
{
    __shared__ __align__(128) char smbuf[NSTG * STG_BYTES];
    uint32_t sb = smem_u32(smbuf);
    const int t    = threadIdx.x;
    const int lane = t & 31;
    const int w    = t >> 5;
    const int wm   = w >> 1;
    const int wn   = w & 1;

    float acc[2][8][4];
    #pragma unroll
    for (int f = 0; f < 2; f++)
        #pragma unroll
        for (int p = 0; p < 8; p++)
            #pragma unroll
            for (int e = 0; e < 4; e++) acc[f][p][e] = 0.f;

    const int NCH = K3 / CHUNK;   // 96

    gemm_load_chunk(sb, Ag, Bg, mblock, nblock, 0);
    gemm_load_chunk(sb, Ag, Bg, mblock, nblock, 1);

    for (int c = 0; c < NCH; c++) {
        if (c < NCH - 1) asm volatile("cp.async.wait_group 1;" ::: "memory");
        else             asm volatile("cp.async.wait_group 0;" ::: "memory");
        __syncthreads();
        if (c + 2 < NCH) gemm_load_chunk(sb, Ag, Bg, mblock, nblock, c + 2);

        uint32_t ab = sb + (c % NSTG) * STG_BYTES;
        uint32_t bb = ab + 8192;

        #pragma unroll
        for (int ks = 0; ks < 2; ks++) {
            uint32_t afr[2][4];
            #pragma unroll
            for (int f = 0; f < 2; f++) {
                int r = wm * 32 + f * 16 + (lane & 15);
                int k = ks * 16 + (lane >> 4) * 8;
                ldsm_x4(afr[f], sw_addr(ab, r, k));
            }
            uint32_t bfr[8][2];
            #pragma unroll
            for (int p = 0; p < 4; p++) {
                int n = wn * 64 + p * 16 + ((lane >> 4) & 1) * 8 + (lane & 7);
                int k = ks * 16 + ((lane >> 3) & 1) * 8;
                uint32_t r4[4];
                ldsm_x4(r4, sw_addr(bb, n, k));
                bfr[p * 2][0]     = r4[0];
                bfr[p * 2][1]     = r4[1];
                bfr[p * 2 + 1][0] = r4[2];
                bfr[p * 2 + 1][1] = r4[3];
            }
            #pragma unroll
            for (int f = 0; f < 2; f++)
                #pragma unroll
                for (int p = 0; p < 8; p++)
                    mma16816(acc[f][p], afr[f], bfr[p]);
        }
    }

    #pragma unroll
    for (int f = 0; f < 2; f++) {
        #pragma unroll
        for (int p = 0; p < 8; p++) {
            #pragma unroll
            for (int e2 = 0; e2 < 2; e2++) {
                int m  = mblock + wm * 32 + f * 16 + (lane >> 2) + e2 * 8;
                int n0 = nblock + wn * 64 + p * 8 + ((lane & 3) << 1);
                float v0 = acc[f][p][e2 * 2], v1 = acc[f][p][e2 * 2 + 1];
                if (flavor == 3) {
                    outp[(size_t)m * DDIM + n0]     = v0;
                    outp[(size_t)m * DDIM + n0 + 1] = v1;
                } else {
                    __nv_bfloat16 h0 = __float2bfloat16(v0), h1 = __float2bfloat16(v1);
                    uint32_t hi = pkb2(h0, h1);
                    uint32_t lo = pkb2(__float2bfloat16(v0 - __bfloat162float(h0)),
                                       __float2bfloat16(v1 - __bfloat162float(h1)));
                    int b0 = m >> 11, s = m & 2047, hh = n0 >> 6, d = n0 & 63;
                    int bh = b0 * HH + hh;
                    if (flavor == 0) {
                        size_t o = ((size_t)bh * SS + s) * DH + d;
                        *(uint32_t*)(g_qh + o) = hi;
                        *(uint32_t*)(g_ql + o) = lo;
                    } else {
                        size_t o = ((size_t)bh * LKV + PFX + s) * DH + d;
                        if (flavor == 1) {
                            *(uint32_t*)(g_kh + o) = hi;
                            *(uint32_t*)(g_kl + o) = lo;
                        } else {
                            *(uint32_t*)(g_vh + o) = hi;
                            *(uint32_t*)(g_vl + o) = lo;
                        }
                    }
                }
            }
        }
    }
}

__global__ __launch_bounds__(256, 2) void gemm_qkv_mma()
{
    const int z = blockIdx.z;
    gemm_mma_body(g_a3, g_w3 + (size_t)z * DDIM * K3,
                  blockIdx.y * 128, blockIdx.x * 128, z, nullptr);
}

__global__ __launch_bounds__(256, 2) void gemm_o_mma(float* __restrict__ out)
{
    gemm_mma_body(g_o3, g_w3 + (size_t)3 * DDIM * K3,
                  blockIdx.y * 128, blockIdx.x * 128, 3, out);
}

// ---------------- mma.sync flash attention (paired 64-key softmax) ----------------
// 128 thr / 4 warps; Q-tile 64; KV staged in 4 x 16KB ring (64KB dynamic smem, occ 3).
// Softmax runs once per 64 keys (1 solo 32-key tile + 32 pairs).
#define ATTN_SMEM 65536

__device__ __forceinline__ void attn_load_kv_nc(int t, int bh, int kt, uint32_t base)
{
    #pragma unroll
    for (int i = 0; i < 2; i++) {
        const int row = (t >> 3) + i * 16;
        const int c = t & 7;
        uint32_t off = (uint32_t)(row * 128 + ((c ^ (row & 7)) << 4));
        size_t goff = ((size_t)bh * LKV + kt * 32 + row) * DH + c * 8;
        cpa16(base + off,         g_kh + goff);
        cpa16(base + 4096 + off,  g_kl + goff);
        cpa16(base + 8192 + off,  g_vh + goff);
        cpa16(base + 12288 + off, g_vl + goff);
    }
}

// QK^T for one 32-key tile: sfr[0..3] += Qhi Khi^T + Qhi Klo^T + Qlo Khi^T
__device__ __forceinline__ void qk32(float (*sfr)[4], uint32_t kbb,
        const uint32_t (*qh)[4], const uint32_t (*ql)[4], int lane)
{
    #pragma unroll
    for (int j = 0; j < 4; j++) {
        #pragma unroll
        for (int gk2 = 0; gk2 < 2; gk2++) {
            int row = gk2 * 16 + ((lane >> 4) << 3) + (lane & 7);
            int ch  = 2 * j + ((lane >> 3) & 1);
            uint32_t ah = kbb + row * 128 + ((ch ^ (row & 7)) << 4);
            uint32_t kh4[4], kl4[4];
            ldsm_x4(kh4, ah);
            ldsm_x4(kl4, ah + 4096);
            mma16816(sfr[2 * gk2],     qh[j], kh4);
            mma16816(sfr[2 * gk2 + 1], qh[j], kh4 + 2);
            mma16816(sfr[2 * gk2],     qh[j], kl4);
            mma16816(sfr[2 * gk2 + 1], qh[j], kl4 + 2);
            mma16816(sfr[2 * gk2],     ql[j], kh4);
            mma16816(sfr[2 * gk2 + 1], ql[j], kh4 + 2);
        }
    }
}

__device__ __forceinline__ void addbias32(float (*sfr)[4], int kb, int qrow,
        const float* __restrict__ maskb, const float* __restrict__ biash, int tc)
{
    #pragma unroll
    for (int grp = 0; grp < 4; grp++) {
        int key0 = kb + grp * 8 + tc * 2;
        float mv0 = (key0 >= PFX)     ? maskb[key0 - PFX]     : 0.f;
        float mv1 = (key0 + 1 >= PFX) ? maskb[key0 + 1 - PFX] : 0.f;
        const float* bp = biash + (key0 - qrow + (BIAS_OFF - PFX));
        sfr[grp][0] += bp[0] + mv0;
        sfr[grp][1] += bp[1] + mv1;
        sfr[grp][2] += bp[-8] + mv0;
        sfr[grp][3] += bp[-7] + mv1;
    }
}

template <int NG>
__device__ __forceinline__ void softmax_groups(float (*sfr)[4],
        float* mrow, float* lrow, float (*ofr)[4])
{
    #pragma unroll
    for (int row = 0; row < 2; row++) {
        float mx = sfr[0][row * 2];
        #pragma unroll
        for (int grp = 0; grp < NG; grp++) {
            mx = fmaxf(mx, sfr[grp][row * 2]);
            mx = fmaxf(mx, sfr[grp][row * 2 + 1]);
        }
        mx = fmaxf(mx, __shfl_xor_sync(0xffffffffu, mx, 1));
        mx = fmaxf(mx, __shfl_xor_sync(0xffffffffu, mx, 2));
        float mn = fmaxf(mrow[row], mx);
        float alpha = __expf(mrow[row] - mn);
        mrow[row] = mn;
        float sum = 0.f;
        #pragma unroll
        for (int grp = 0; grp < NG; grp++) {
            float p0 = __expf(sfr[grp][row * 2] - mn);
            float p1 = __expf(sfr[grp][row * 2 + 1] - mn);
            sfr[grp][row * 2] = p0;
            sfr[grp][row * 2 + 1] = p1;
            sum += p0 + p1;
        }
        sum += __shfl_xor_sync(0xffffffffu, sum, 1);
        sum += __shfl_xor_sync(0xffffffffu, sum, 2);
        lrow[row] = lrow[row] * alpha + sum;
        #pragma unroll
        for (int gd = 0; gd < 8; gd++) {
            ofr[gd][row * 2]     *= alpha;
            ofr[gd][row * 2 + 1] *= alpha;
        }
    }
}

// PV for one 32-key tile: O += Phi Vhi + Phi Vlo + Plo Vhi (P taken from sfr[0..3])
__device__ __forceinline__ void pv32(float (*ofr)[4], const float (*sfr)[4],
                                     uint32_t vbb, int lane)
{
    uint32_t phi[2][4], plo[2][4];
    #pragma unroll
    for (int jk = 0; jk < 2; jk++) {
        #pragma unroll
        for (int e = 0; e < 4; e++) {
            int grp = 2 * jk + (e >> 1);
            int i0  = (e & 1) * 2;
            float p0 = sfr[grp][i0], p1 = sfr[grp][i0 + 1];
            __nv_bfloat16 h0 = __float2bfloat16(p0), h1 = __float2bfloat16(p1);
            phi[jk][e] = pkb2(h0, h1);
            plo[jk][e] = pkb2(__float2bfloat16(p0 - __bfloat162float(h0)),
                              __float2bfloat16(p1 - __bfloat162float(h1)));
        }
    }
    #pragma unroll
    for (int jk = 0; jk < 2; jk++) {
        #pragma unroll
        for (int gd2 = 0; gd2 < 4; gd2++) {
            int row = jk * 16 + (((lane >> 3) & 1) << 3) + (lane & 7);
            int ch  = 2 * gd2 + (lane >> 4);
            uint32_t av = vbb + row * 128 + ((ch ^ (row & 7)) << 4);
            uint32_t vh4[4], vl4[4];
            ldsm_x4_t(vh4, av);
            ldsm_x4_t(vl4, av + 4096);
            mma16816(ofr[2 * gd2],     phi[jk], vh4);
            mma16816(ofr[2 * gd2 + 1], phi[jk], vh4 + 2);
            mma16816(ofr[2 * gd2],     phi[jk], vl4);
            mma16816(ofr[2 * gd2 + 1], phi[jk], vl4 + 2);
            mma16816(ofr[2 * gd2],     plo[jk], vh4);
            mma16816(ofr[2 * gd2 + 1], plo[jk], vh4 + 2);
        }
    }
}

__global__ __launch_bounds__(128, 3) void attn_mma_kernel(const float* __restrict__ mask)
{
    extern __shared__ char kvsm[];
    uint32_t sb0 = smem_u32(kvsm);
    const int t = threadIdx.x, lane = t & 31, w = t >> 5;
    const int g = lane >> 2, tc = lane & 3;
    const int h = blockIdx.y, b = blockIdx.z, bh = b * HH + h;
    const int qb = blockIdx.x * 64;
    const int m0 = qb + w * 16;

    uint32_t qh[4][4], ql[4][4];
    {
        const __nv_bfloat16* qhp = g_qh + ((size_t)bh * SS + m0) * DH;
        const __nv_bfloat16* qlp = g_ql + ((size_t)bh * SS + m0) * DH;
        #pragma unroll
        for (int j = 0; j < 4; j++)
            #pragma unroll
            for (int e = 0; e < 4; e++) {
                int r = g + (e & 1) * 8;
                int k = j * 16 + tc * 2 + (e >> 1) * 8;
                qh[j][e] = *(const uint32_t*)(qhp + (size_t)r * DH + k);
                ql[j][e] = *(const uint32_t*)(qlp + (size_t)r * DH + k);
            }
    }

    float ofr[8][4];
    #pragma unroll
    for (int i = 0; i < 8; i++)
        #pragma unroll
        for (int e = 0; e < 4; e++) ofr[i][e] = 0.f;
    float mrow[2] = {-INFINITY, -INFINITY};
    float lrow[2] = {0.f, 0.f};

    const float* maskb = mask + b * SS;
    const float* biash = g_bias + h * BIAS_STRIDE;

    // prologue: tiles 0,1,2 in flight (one commit each)
    attn_load_kv_nc(t, bh, 0, sb0);             CP_COMMIT();
    attn_load_kv_nc(t, bh, 1, sb0 + 16384);     CP_COMMIT();
    attn_load_kv_nc(t, bh, 2, sb0 + 32768);     CP_COMMIT();

    float sfr[8][4];

    // ---- solo tile 0 (prefix region) ----
    asm volatile("cp.async.wait_group 2;" ::: "memory");
    __syncthreads();
    #pragma unroll
    for (int i = 0; i < 4; i++)
        #pragma unroll
        for (int e = 0; e < 4; e++) sfr[i][e] = 0.f;
    qk32(sfr, sb0, qh, ql, lane);
    addbias32(sfr, 0, m0 + g, maskb, biash, tc);
    softmax_groups<4>(sfr, mrow, lrow, ofr);
    pv32(ofr, sfr, sb0 + 8192, lane);

    // ---- 32 pairs: tiles (2p+1, 2p+2) ----
    for (int p = 0; p < 32; p++) {
        const int ta = 2 * p + 1, tb = 2 * p + 2;
        const uint32_t ba = sb0 + (ta & 3) * 16384;
        const uint32_t bbb = sb0 + (tb & 3) * 16384;
        __syncthreads();                                   // prior reads of reused bufs done
        if (p < 31) {
            attn_load_kv_nc(t, bh, 2 * p + 3, sb0 + ((2 * p + 3) & 3) * 16384);
            attn_load_kv_nc(t, bh, 2 * p + 4, sb0 + ((2 * p + 4) & 3) * 16384);
            CP_COMMIT();
            asm volatile("cp.async.wait_group 1;" ::: "memory");
        } else {
            asm volatile("cp.async.wait_group 0;" ::: "memory");
        }
        __syncthreads();                                   // tiles ta, tb visible to all

        #pragma unroll
        for (int i = 0; i < 8; i++)
            #pragma unroll
            for (int e = 0; e < 4; e++) sfr[i][e] = 0.f;
        qk32(sfr,     ba,  qh, ql, lane);
        qk32(sfr + 4, bbb, qh, ql, lane);
        addbias32(sfr,     ta * 32, m0 + g, maskb, biash, tc);
        addbias32(sfr + 4, tb * 32, m0 + g, maskb, biash, tc);
        softmax_groups<8>(sfr, mrow, lrow, ofr);
        pv32(ofr, sfr,     ba  + 8192, lane);
        pv32(ofr, sfr + 4, bbb + 8192, lane);
    }

    // ---- epilogue: normalize, split hi/lo, write o3 = [hi|hi|lo] ----
    float inv0 = 1.f / lrow[0], inv1 = 1.f / lrow[1];
    #pragma unroll
    for (int gd = 0; gd < 8; gd++) {
        int d0 = gd * 8 + tc * 2;
        int k  = h * 64 + d0;
        #pragma unroll
        for (int row = 0; row < 2; row++) {
            float v0 = ofr[gd][row * 2]     * (row ? inv1 : inv0);
            float v1 = ofr[gd][row * 2 + 1] * (row ? inv1 : inv0);
            __nv_bfloat16 h0 = __float2bfloat16(v0), h1 = __float2bfloat16(v1);
            uint32_t hi = pkb2(h0, h1);
            uint32_t lo = pkb2(__float2bfloat16(v0 - __bfloat162float(h0)),
                               __float2bfloat16(v1 - __bfloat162float(h1)));
            size_t rbase = ((size_t)(b * SS + m0 + g + row * 8)) * K3 + k;
            *(uint32_t*)(g_o3 + rbase)        = hi;
            *(uint32_t*)(g_o3 + rbase + 1024) = hi;
            *(uint32_t*)(g_o3 + rbase + 2048) = lo;
        }
    }
}

// ---------------- launch ----------------
extern "C" void kernel_launch(void* const* d_in, const int* in_sizes, int n_in,
                              void* d_out, int out_size)
{
    const float* hidden = (const float*)d_in[0];
    const float* mask   = (const float*)d_in[1];
    const float* pk     = (const float*)d_in[2];
    const float* pv     = (const float*)d_in[3];
    const float* Wq     = (const float*)d_in[4];
    const float* Wk     = (const float*)d_in[5];
    const float* Wv     = (const float*)d_in[6];
    const float* Wo     = (const float*)d_in[7];
    const float* rel    = (const float*)d_in[8];
    float* out = (float*)d_out;

    cudaFuncSetAttribute(attn_mma_kernel,
                         cudaFuncAttributeMaxDynamicSharedMemorySize, ATTN_SMEM);

    bias_init_kernel<<<(HH * 4127 + 255) / 256, 256>>>(rel);
    prefix_copy_kernel<<<(BB * HH * PFX * DH + 255) / 256, 256>>>(pk, pv);
    split_hidden_kernel<<<(BB * SS * DDIM / 4 + 255) / 256, 256>>>(hidden);
    split_w_kernel<<<dim3(32, 32, 4), 256>>>(Wq, Wk, Wv, Wo);
    gemm_qkv_mma<<<dim3(8, 32, 3), 256>>>();
    attn_mma_kernel<<<dim3(SS / 64, HH, BB), 128, ATTN_SMEM>>>(mask);
    gemm_o_mma<<<dim3(8, 32), 256>>>(out);
}

// round 10
// speedup vs baseline: 2.6907x; 1.0210x over previous
#include <cuda_runtime.h>
#include <cuda_bf16.h>
#include <math.h>
#include <stdint.h>

// Problem constants
#define BB   2
#define HH   16
#define SS   2048
#define DDIM 1024
#define DH   64
#define PFX  32
#define LKV  2080          // PFX + SS = 65 * 32
#define BIAS_STRIDE 4160
#define BIAS_OFF 2079

// ---------------- scratch (static device globals; no allocation) ----------------
__device__ float g_bias[HH * BIAS_STRIDE];                   // [h][rel+2079]
__device__ __nv_bfloat16 g_ah[(size_t)BB * SS * DDIM];       // hidden hi [m][k]
__device__ __nv_bfloat16 g_al[(size_t)BB * SS * DDIM];       // hidden lo
__device__ __nv_bfloat16 g_wh[(size_t)4 * DDIM * DDIM];      // W hi, transposed [n][k]
__device__ __nv_bfloat16 g_wl[(size_t)4 * DDIM * DDIM];      // W lo
__device__ __nv_bfloat16 g_oh[(size_t)BB * SS * DDIM];       // attn-out hi
__device__ __nv_bfloat16 g_ol[(size_t)BB * SS * DDIM];       // attn-out lo
__device__ __nv_bfloat16 g_qh[(size_t)BB * HH * SS * DH];    // [bh][s][d]
__device__ __nv_bfloat16 g_ql[(size_t)BB * HH * SS * DH];
__device__ __nv_bfloat16 g_kh[(size_t)BB * HH * LKV * DH];   // [bh][key][d]
__device__ __nv_bfloat16 g_kl[(size_t)BB * HH * LKV * DH];
__device__ __nv_bfloat16 g_vh[(size_t)BB * HH * LKV * DH];
__device__ __nv_bfloat16 g_vl[(size_t)BB * HH * LKV * DH];

// ======================= PTX helpers (sm_80-class only) =======================
__device__ __forceinline__ uint32_t smem_u32(const void* p) {
    uint32_t a;
    asm("{ .reg .u64 t; cvta.to.shared.u64 t, %1; cvt.u32.u64 %0, t; }" : "=r"(a) : "l"(p));
    return a;
}
__device__ __forceinline__ void cpa16(uint32_t dst, const void* src) {
    asm volatile("cp.async.cg.shared.global [%0], [%1], 16;" :: "r"(dst), "l"(src));
}
__device__ __forceinline__ void ldsm_x4(uint32_t* r, uint32_t addr) {
    asm volatile("ldmatrix.sync.aligned.m8n8.x4.shared.b16 {%0,%1,%2,%3}, [%4];"
                 : "=r"(r[0]), "=r"(r[1]), "=r"(r[2]), "=r"(r[3]) : "r"(addr));
}
__device__ __forceinline__ void ldsm_x4_t(uint32_t* r, uint32_t addr) {
    asm volatile("ldmatrix.sync.aligned.m8n8.x4.trans.shared.b16 {%0,%1,%2,%3}, [%4];"
                 : "=r"(r[0]), "=r"(r[1]), "=r"(r[2]), "=r"(r[3]) : "r"(addr));
}
__device__ __forceinline__ void mma16816(float* d, const uint32_t* a, const uint32_t* b) {
    asm volatile("mma.sync.aligned.m16n8k16.row.col.f32.bf16.bf16.f32 "
                 "{%0,%1,%2,%3}, {%4,%5,%6,%7}, {%8,%9}, {%0,%1,%2,%3};"
                 : "+f"(d[0]), "+f"(d[1]), "+f"(d[2]), "+f"(d[3])
                 : "r"(a[0]), "r"(a[1]), "r"(a[2]), "r"(a[3]), "r"(b[0]), "r"(b[1]));
}
__device__ __forceinline__ uint32_t pkb2(__nv_bfloat16 a, __nv_bfloat16 b) {
    uint16_t ua = *(uint16_t*)&a, ub = *(uint16_t*)&b;
    return (uint32_t)ua | ((uint32_t)ub << 16);
}
// GEMM smem swizzle: rows of 64B (32 bf16), quad = 16B unit
__device__ __forceinline__ uint32_t sw_addr(uint32_t base, int r, int k) {
    int quad = k >> 3;
    int sw   = quad ^ ((r >> 1) & 3);
    return base + r * 64 + sw * 16 + (k & 7) * 2;
}
#define CP_COMMIT() asm volatile("cp.async.commit_group;" ::: "memory")

// ---------------- fused preprocessing kernel ----------------
// blocks [0,4096): split_hidden   (1,048,576 float4 units)
// blocks [4096,8192): split_w     (4 weights x 32x32 tile-blocks)
// blocks [8192,8450): bias table  (66,032 entries)
// blocks [8450,8706): prefix K/V  (65,536 entries)
#define PREP_BLOCKS 8706

__global__ __launch_bounds__(256) void prep_kernel(
        const float* __restrict__ hidden,
        const float* __restrict__ Wq, const float* __restrict__ Wk,
        const float* __restrict__ Wv, const float* __restrict__ Wo,
        const float* __restrict__ pk, const float* __restrict__ pv,
        const float* __restrict__ rel_table)
{
    __shared__ float tile[32][33];
    const int bid = blockIdx.x;
    const int tid = threadIdx.x;

    if (bid < 4096) {
        // ---- split hidden -> g_ah / g_al (linear layout) ----
        int i4 = bid * 256 + tid;
        float4 x = *(const float4*)(hidden + (size_t)i4 * 4);
        __nv_bfloat16 h0 = __float2bfloat16(x.x), h1 = __float2bfloat16(x.y);
        __nv_bfloat16 h2 = __float2bfloat16(x.z), h3 = __float2bfloat16(x.w);
        uint32_t hiA = pkb2(h0, h1), hiB = pkb2(h2, h3);
        uint32_t loA = pkb2(__float2bfloat16(x.x - __bfloat162float(h0)),
                            __float2bfloat16(x.y - __bfloat162float(h1)));
        uint32_t loB = pkb2(__float2bfloat16(x.z - __bfloat162float(h2)),
                            __float2bfloat16(x.w - __bfloat162float(h3)));
        size_t b = (size_t)i4 * 4;
        uint32_t* ph = (uint32_t*)(g_ah + b);
        ph[0] = hiA; ph[1] = hiB;
        uint32_t* pl = (uint32_t*)(g_al + b);
        pl[0] = loA; pl[1] = loB;
    } else if (bid < 8192) {
        // ---- split + transpose weights -> g_wh / g_wl ----
        int zz = bid - 4096;
        int z  = zz >> 10;
        int zb = zz & 1023;
        int n0 = (zb & 31) * 32, k0 = (zb >> 5) * 32;
        const float* W = (z == 0) ? Wq : (z == 1) ? Wk : (z == 2) ? Wv : Wo;
        __nv_bfloat16* dh = g_wh + (size_t)z * DDIM * DDIM;
        __nv_bfloat16* dl = g_wl + (size_t)z * DDIM * DDIM;
        const int tx = tid & 31, ty0 = tid >> 5;
        #pragma unroll
        for (int r = 0; r < 4; r++) {
            int ty = ty0 + r * 8;
            tile[ty][tx] = W[(size_t)(k0 + ty) * DDIM + n0 + tx];
        }
        __syncthreads();
        #pragma unroll
        for (int r = 0; r < 4; r++) {
            int ty = ty0 + r * 8;
            float x = tile[tx][ty];              // = W[k0+tx][n0+ty]
            __nv_bfloat16 h = __float2bfloat16(x);
            __nv_bfloat16 l = __float2bfloat16(x - __bfloat162float(h));
            size_t b = (size_t)(n0 + ty) * DDIM + (k0 + tx);
            dh[b] = h;
            dl[b] = l;
        }
    } else if (bid < 8450) {
        // ---- bias table ----
        int idx = (bid - 8192) * 256 + tid;
        if (idx < HH * 4127) {
            int h   = idx / 4127;
            int r   = idx - h * 4127;
            int rel = r - BIAS_OFF;
            int ret = (rel > 0) ? 16 : 0;
            int n   = rel < 0 ? -rel : rel;
            int bkt;
            if (n < 8) {
                bkt = n;
            } else {
                float nf = (float)n;
                int vl = 8 + (int)(logf(nf * 0.125f) / 2.772588722239781f * 8.0f);
                bkt = vl < 15 ? vl : 15;
            }
            bkt += ret;
            g_bias[h * BIAS_STRIDE + r] = rel_table[bkt * HH + h];
        }
    } else {
        // ---- prefix K/V copy (fp32 -> bf16 hi/lo) ----
        int idx = (bid - 8450) * 256 + tid;
        int d  = idx & 63;
        int p  = (idx >> 6) & 31;
        int bh = idx >> 11;
        size_t o = ((size_t)bh * LKV + p) * DH + d;
        float kx = pk[idx], vx = pv[idx];
        __nv_bfloat16 khf = __float2bfloat16(kx);
        __nv_bfloat16 vhf = __float2bfloat16(vx);
        g_kh[o] = khf;
        g_kl[o] = __float2bfloat16(kx - __bfloat162float(khf));
        g_vh[o] = vhf;
        g_vl[o] = __float2bfloat16(vx - __bfloat162float(vhf));
    }
}

// ---------------- mma.sync bf16 GEMM: C = [Ahi|Ahi|Alo] * [Whi|Wlo|Whi]^T ----------------
// Region addressing over separate hi/lo planes. Chunk = 32 k-elems, NCH = 96:
//   chunks 0-31:  Ah x Wh @ off c*32
//   chunks 32-63: Ah x Wl @ off (c-32)*32
//   chunks 64-95: Al x Wh @ off (c-64)*32
#define CHUNK 32
#define NSTG 3
#define STG_BYTES 16384
#define NCH 96

__device__ __forceinline__ void gemm_load_chunk(uint32_t sb,
        const __nv_bfloat16* __restrict__ Ah, const __nv_bfloat16* __restrict__ Al,
        const __nv_bfloat16* __restrict__ Wh, const __nv_bfloat16* __restrict__ Wl,
        int mblock, int nblock, int c)
{
    const int t = threadIdx.x;
    const int st = c % NSTG;
    uint32_t ab = sb + st * STG_BYTES;
    uint32_t bb = ab + 8192;
    const __nv_bfloat16* Ag = (c < 64) ? Ah : Al;
    const __nv_bfloat16* Wg = (c < 32 || c >= 64) ? Wh : Wl;
    const int co = (c & 31) * CHUNK;
    #pragma unroll
    for (int i = 0; i < 2; i++) {
        int idx = t + i * 256;
        int r = idx >> 2, q = idx & 3;
        uint32_t soff = (uint32_t)(r * 64 + ((q ^ ((r >> 1) & 3)) << 4));
        const char* as = (const char*)(Ag + (size_t)(mblock + r) * DDIM + co + q * 8);
        const char* bs = (const char*)(Wg + (size_t)(nblock + r) * DDIM + co + q * 8);
        cpa16(ab + soff, as);
        cpa16(bb + soff, bs);
    }
    CP_COMMIT();
}

__device__ __forceinline__ void gemm_mma_body(
        const __nv_bfloat16* __restrict__ Ah, const __nv_bfloat16* __restrict__ Al,
        const __nv_bfloat16* __restrict__ Wh, const __nv_bfloat16* __restrict__ Wl,
        int mblock, int nblock, int flavor, float* __restrict__ outp)
{
    __shared__ __align__(128) char smbuf[NSTG * STG_BYTES];
    uint32_t sb = smem_u32(smbuf);
    const int t    = threadIdx.x;
    const int lane = t & 31;
    const int w    = t >> 5;
    const int wm   = w >> 1;
    const int wn   = w & 1;

    float acc[2][8][4];
    #pragma unroll
    for (int f = 0; f < 2; f++)
        #pragma unroll
        for (int p = 0; p < 8; p++)
            #pragma unroll
            for (int e = 0; e < 4; e++) acc[f][p][e] = 0.f;

    gemm_load_chunk(sb, Ah, Al, Wh, Wl, mblock, nblock, 0);
    gemm_load_chunk(sb, Ah, Al, Wh, Wl, mblock, nblock, 1);

    for (int c = 0; c < NCH; c++) {
        if (c < NCH - 1) asm volatile("cp.async.wait_group 1;" ::: "memory");
        else             asm volatile("cp.async.wait_group 0;" ::: "memory");
        __syncthreads();
        if (c + 2 < NCH) gemm_load_chunk(sb, Ah, Al, Wh, Wl, mblock, nblock, c + 2);

        uint32_t ab = sb + (c % NSTG) * STG_BYTES;
        uint32_t bb = ab + 8192;

        #pragma unroll
        for (int ks = 0; ks < 2; ks++) {
            uint32_t afr[2][4];
            #pragma unroll
            for (int f = 0; f < 2; f++) {
                int r = wm * 32 + f * 16 + (lane & 15);
                int k = ks * 16 + (lane >> 4) * 8;
                ldsm_x4(afr[f], sw_addr(ab, r, k));
            }
            uint32_t bfr[8][2];
            #pragma unroll
            for (int p = 0; p < 4; p++) {
                int n = wn * 64 + p * 16 + ((lane >> 4) & 1) * 8 + (lane & 7);
                int k = ks * 16 + ((lane >> 3) & 1) * 8;
                uint32_t r4[4];
                ldsm_x4(r4, sw_addr(bb, n, k));
                bfr[p * 2][0]     = r4[0];
                bfr[p * 2][1]     = r4[1];
                bfr[p * 2 + 1][0] = r4[2];
                bfr[p * 2 + 1][1] = r4[3];
            }
            #pragma unroll
            for (int f = 0; f < 2; f++)
                #pragma unroll
                for (int p = 0; p < 8; p++)
                    mma16816(acc[f][p], afr[f], bfr[p]);
        }
    }

    #pragma unroll
    for (int f = 0; f < 2; f++) {
        #pragma unroll
        for (int p = 0; p < 8; p++) {
            #pragma unroll
            for (int e2 = 0; e2 < 2; e2++) {
                int m  = mblock + wm * 32 + f * 16 + (lane >> 2) + e2 * 8;
                int n0 = nblock + wn * 64 + p * 8 + ((lane & 3) << 1);
                float v0 = acc[f][p][e2 * 2], v1 = acc[f][p][e2 * 2 + 1];
                if (flavor == 3) {
                    outp[(size_t)m * DDIM + n0]     = v0;
                    outp[(size_t)m * DDIM + n0 + 1] = v1;
                } else {
                    __nv_bfloat16 h0 = __float2bfloat16(v0), h1 = __float2bfloat16(v1);
                    uint32_t hi = pkb2(h0, h1);
                    uint32_t lo = pkb2(__float2bfloat16(v0 - __bfloat162float(h0)),
                                       __float2bfloat16(v1 - __bfloat162float(h1)));
                    int b0 = m >> 11, s = m & 2047, hh = n0 >> 6, d = n0 & 63;
                    int bh = b0 * HH + hh;
                    if (flavor == 0) {
                        size_t o = ((size_t)bh * SS + s) * DH + d;
                        *(uint32_t*)(g_qh + o) = hi;
                        *(uint32_t*)(g_ql + o) = lo;
                    } else {
                        size_t o = ((size_t)bh * LKV + PFX + s) * DH + d;
                        if (flavor == 1) {
                            *(uint32_t*)(g_kh + o) = hi;
                            *(uint32_t*)(g_kl + o) = lo;
                        } else {
                            *(uint32_t*)(g_vh + o) = hi;
                            *(uint32_t*)(g_vl + o) = lo;
                        }
                    }
                }
            }
        }
    }
}

__global__ __launch_bounds__(256, 2) void gemm_qkv_mma()
{
    const int z = blockIdx.z;
    gemm_mma_body(g_ah, g_al,
                  g_wh + (size_t)z * DDIM * DDIM, g_wl + (size_t)z * DDIM * DDIM,
                  blockIdx.y * 128, blockIdx.x * 128, z, nullptr);
}

__global__ __launch_bounds__(256, 2) void gemm_o_mma(float* __restrict__ out)
{
    gemm_mma_body(g_oh, g_ol,
                  g_wh + (size_t)3 * DDIM * DDIM, g_wl + (size_t)3 * DDIM * DDIM,
                  blockIdx.y * 128, blockIdx.x * 128, 3, out);
}

// ---------------- mma.sync flash attention (paired 64-key softmax) ----------------
#define ATTN_SMEM 65536

__device__ __forceinline__ void attn_load_kv_nc(int t, int bh, int kt, uint32_t base)
{
    #pragma unroll
    for (int i = 0; i < 2; i++) {
        const int row = (t >> 3) + i * 16;
        const int c = t & 7;
        uint32_t off = (uint32_t)(row * 128 + ((c ^ (row & 7)) << 4));
        size_t goff = ((size_t)bh * LKV + kt * 32 + row) * DH + c * 8;
        cpa16(base + off,         g_kh + goff);
        cpa16(base + 4096 + off,  g_kl + goff);
        cpa16(base + 8192 + off,  g_vh + goff);
        cpa16(base + 12288 + off, g_vl + goff);
    }
}

__device__ __forceinline__ void qk32(float (*sfr)[4], uint32_t kbb,
        const uint32_t (*qh)[4], const uint32_t (*ql)[4], int lane)
{
    #pragma unroll
    for (int j = 0; j < 4; j++) {
        #pragma unroll
        for (int gk2 = 0; gk2 < 2; gk2++) {
            int row = gk2 * 16 + ((lane >> 4) << 3) + (lane & 7);
            int ch  = 2 * j + ((lane >> 3) & 1);
            uint32_t ah = kbb + row * 128 + ((ch ^ (row & 7)) << 4);
            uint32_t kh4[4], kl4[4];
            ldsm_x4(kh4, ah);
            ldsm_x4(kl4, ah + 4096);
            mma16816(sfr[2 * gk2],     qh[j], kh4);
            mma16816(sfr[2 * gk2 + 1], qh[j], kh4 + 2);
            mma16816(sfr[2 * gk2],     qh[j], kl4);
            mma16816(sfr[2 * gk2 + 1], qh[j], kl4 + 2);
            mma16816(sfr[2 * gk2],     ql[j], kh4);
            mma16816(sfr[2 * gk2 + 1], ql[j], kh4 + 2);
        }
    }
}

__device__ __forceinline__ void addbias32(float (*sfr)[4], int kb, int qrow,
        const float* __restrict__ maskb, const float* __restrict__ biash, int tc)
{
    #pragma unroll
    for (int grp = 0; grp < 4; grp++) {
        int key0 = kb + grp * 8 + tc * 2;
        float mv0 = (key0 >= PFX)     ? maskb[key0 - PFX]     : 0.f;
        float mv1 = (key0 + 1 >= PFX) ? maskb[key0 + 1 - PFX] : 0.f;
        const float* bp = biash + (key0 - qrow + (BIAS_OFF - PFX));
        sfr[grp][0] += bp[0] + mv0;
        sfr[grp][1] += bp[1] + mv1;
        sfr[grp][2] += bp[-8] + mv0;
        sfr[grp][3] += bp[-7] + mv1;
    }
}

template <int NG>
__device__ __forceinline__ void softmax_groups(float (*sfr)[4],
        float* mrow, float* lrow, float (*ofr)[4])
{
    #pragma unroll
    for (int row = 0; row < 2; row++) {
        float mx = sfr[0][row * 2];
        #pragma unroll
        for (int grp = 0; grp < NG; grp++) {
            mx = fmaxf(mx, sfr[grp][row * 2]);
            mx = fmaxf(mx, sfr[grp][row * 2 + 1]);
        }
        mx = fmaxf(mx, __shfl_xor_sync(0xffffffffu, mx, 1));
        mx = fmaxf(mx, __shfl_xor_sync(0xffffffffu, mx, 2));
        float mn = fmaxf(mrow[row], mx);
        float alpha = __expf(mrow[row] - mn);
        mrow[row] = mn;
        float sum = 0.f;
        #pragma unroll
        for (int grp = 0; grp < NG; grp++) {
            float p0 = __expf(sfr[grp][row * 2] - mn);
            float p1 = __expf(sfr[grp][row * 2 + 1] - mn);
            sfr[grp][row * 2] = p0;
            sfr[grp][row * 2 + 1] = p1;
            sum += p0 + p1;
        }
        sum += __shfl_xor_sync(0xffffffffu, sum, 1);
        sum += __shfl_xor_sync(0xffffffffu, sum, 2);
        lrow[row] = lrow[row] * alpha + sum;
        #pragma unroll
        for (int gd = 0; gd < 8; gd++) {
            ofr[gd][row * 2]     *= alpha;
            ofr[gd][row * 2 + 1] *= alpha;
        }
    }
}

__device__ __forceinline__ void pv32(float (*ofr)[4], const float (*sfr)[4],
                                     uint32_t vbb, int lane)
{
    uint32_t phi[2][4], plo[2][4];
    #pragma unroll
    for (int jk = 0; jk < 2; jk++) {
        #pragma unroll
        for (int e = 0; e < 4; e++) {
            int grp = 2 * jk + (e >> 1);
            int i0  = (e & 1) * 2;
            float p0 = sfr[grp][i0], p1 = sfr[grp][i0 + 1];
            __nv_bfloat16 h0 = __float2bfloat16(p0), h1 = __float2bfloat16(p1);
            phi[jk][e] = pkb2(h0, h1);
            plo[jk][e] = pkb2(__float2bfloat16(p0 - __bfloat162float(h0)),
                              __float2bfloat16(p1 - __bfloat162float(h1)));
        }
    }
    #pragma unroll
    for (int jk = 0; jk < 2; jk++) {
        #pragma unroll
        for (int gd2 = 0; gd2 < 4; gd2++) {
            int row = jk * 16 + (((lane >> 3) & 1) << 3) + (lane & 7);
            int ch  = 2 * gd2 + (lane >> 4);
            uint32_t av = vbb + row * 128 + ((ch ^ (row & 7)) << 4);
            uint32_t vh4[4], vl4[4];
            ldsm_x4_t(vh4, av);
            ldsm_x4_t(vl4, av + 4096);
            mma16816(ofr[2 * gd2],     phi[jk], vh4);
            mma16816(ofr[2 * gd2 + 1], phi[jk], vh4 + 2);
            mma16816(ofr[2 * gd2],     phi[jk], vl4);
            mma16816(ofr[2 * gd2 + 1], phi[jk], vl4 + 2);
            mma16816(ofr[2 * gd2],     plo[jk], vh4);
            mma16816(ofr[2 * gd2 + 1], plo[jk], vh4 + 2);
        }
    }
}

__global__ __launch_bounds__(128, 3) void attn_mma_kernel(const float* __restrict__ mask)
{
    extern __shared__ char kvsm[];
    uint32_t sb0 = smem_u32(kvsm);
    const int t = threadIdx.x, lane = t & 31, w = t >> 5;
    const int g = lane >> 2, tc = lane & 3;
    const int h = blockIdx.y, b = blockIdx.z, bh = b * HH + h;
    const int qb = blockIdx.x * 64;
    const int m0 = qb + w * 16;

    uint32_t qh[4][4], ql[4][4];
    {
        const __nv_bfloat16* qhp = g_qh + ((size_t)bh * SS + m0) * DH;
        const __nv_bfloat16* qlp = g_ql + ((size_t)bh * SS + m0) * DH;
        #pragma unroll
        for (int j = 0; j < 4; j++)
            #pragma unroll
            for (int e = 0; e < 4; e++) {
                int r = g + (e & 1) * 8;
                int k = j * 16 + tc * 2 + (e >> 1) * 8;
                qh[j][e] = *(const uint32_t*)(qhp + (size_t)r * DH + k);
                ql[j][e] = *(const uint32_t*)(qlp + (size_t)r * DH + k);
            }
    }

    float ofr[8][4];
    #pragma unroll
    for (int i = 0; i < 8; i++)
        #pragma unroll
        for (int e = 0; e < 4; e++) ofr[i][e] = 0.f;
    float mrow[2] = {-INFINITY, -INFINITY};
    float lrow[2] = {0.f, 0.f};

    const float* maskb = mask + b * SS;
    const float* biash = g_bias + h * BIAS_STRIDE;

    attn_load_kv_nc(t, bh, 0, sb0);             CP_COMMIT();
    attn_load_kv_nc(t, bh, 1, sb0 + 16384);     CP_COMMIT();
    attn_load_kv_nc(t, bh, 2, sb0 + 32768);     CP_COMMIT();

    float sfr[8][4];

    // ---- solo tile 0 (prefix region) ----
    asm volatile("cp.async.wait_group 2;" ::: "memory");
    __syncthreads();
    #pragma unroll
    for (int i = 0; i < 4; i++)
        #pragma unroll
        for (int e = 0; e < 4; e++) sfr[i][e] = 0.f;
    qk32(sfr, sb0, qh, ql, lane);
    addbias32(sfr, 0, m0 + g, maskb, biash, tc);
    softmax_groups<4>(sfr, mrow, lrow, ofr);
    pv32(ofr, sfr, sb0 + 8192, lane);

    // ---- 32 pairs: tiles (2p+1, 2p+2) ----
    for (int p = 0; p < 32; p++) {
        const int ta = 2 * p + 1, tb = 2 * p + 2;
        const uint32_t ba = sb0 + (ta & 3) * 16384;
        const uint32_t bbb = sb0 + (tb & 3) * 16384;
        __syncthreads();
        if (p < 31) {
            attn_load_kv_nc(t, bh, 2 * p + 3, sb0 + ((2 * p + 3) & 3) * 16384);
            attn_load_kv_nc(t, bh, 2 * p + 4, sb0 + ((2 * p + 4) & 3) * 16384);
            CP_COMMIT();
            asm volatile("cp.async.wait_group 1;" ::: "memory");
        } else {
            asm volatile("cp.async.wait_group 0;" ::: "memory");
        }
        __syncthreads();

        #pragma unroll
        for (int i = 0; i < 8; i++)
            #pragma unroll
            for (int e = 0; e < 4; e++) sfr[i][e] = 0.f;
        qk32(sfr,     ba,  qh, ql, lane);
        qk32(sfr + 4, bbb, qh, ql, lane);
        addbias32(sfr,     ta * 32, m0 + g, maskb, biash, tc);
        addbias32(sfr + 4, tb * 32, m0 + g, maskb, biash, tc);
        softmax_groups<8>(sfr, mrow, lrow, ofr);
        pv32(ofr, sfr,     ba  + 8192, lane);
        pv32(ofr, sfr + 4, bbb + 8192, lane);
    }

    // ---- epilogue: normalize, split hi/lo, write g_oh / g_ol ----
    float inv0 = 1.f / lrow[0], inv1 = 1.f / lrow[1];
    #pragma unroll
    for (int gd = 0; gd < 8; gd++) {
        int d0 = gd * 8 + tc * 2;
        int k  = h * 64 + d0;
        #pragma unroll
        for (int row = 0; row < 2; row++) {
            float v0 = ofr[gd][row * 2]     * (row ? inv1 : inv0);
            float v1 = ofr[gd][row * 2 + 1] * (row ? inv1 : inv0);
            __nv_bfloat16 h0 = __float2bfloat16(v0), h1 = __float2bfloat16(v1);
            uint32_t hi = pkb2(h0, h1);
            uint32_t lo = pkb2(__float2bfloat16(v0 - __bfloat162float(h0)),
                               __float2bfloat16(v1 - __bfloat162float(h1)));
            size_t rbase = ((size_t)(b * SS + m0 + g + row * 8)) * DDIM + k;
            *(uint32_t*)(g_oh + rbase) = hi;
            *(uint32_t*)(g_ol + rbase) = lo;
        }
    }
}

// ---------------- launch ----------------
extern "C" void kernel_launch(void* const* d_in, const int* in_sizes, int n_in,
                              void* d_out, int out_size)
{
    const float* hidden = (const float*)d_in[0];
    const float* mask   = (const float*)d_in[1];
    const float* pk     = (const float*)d_in[2];
    const float* pv     = (const float*)d_in[3];
    const float* Wq     = (const float*)d_in[4];
    const float* Wk     = (const float*)d_in[5];
    const float* Wv     = (const float*)d_in[6];
    const float* Wo     = (const float*)d_in[7];
    const float* rel    = (const float*)d_in[8];
    float* out = (float*)d_out;

    cudaFuncSetAttribute(attn_mma_kernel,
                         cudaFuncAttributeMaxDynamicSharedMemorySize, ATTN_SMEM);

    prep_kernel<<<PREP_BLOCKS, 256>>>(hidden, Wq, Wk, Wv, Wo, pk, pv, rel);
    gemm_qkv_mma<<<dim3(8, 32, 3), 256>>>();
    attn_mma_kernel<<<dim3(SS / 64, HH, BB), 128, ATTN_SMEM>>>(mask);
    gemm_o_mma<<<dim3(8, 32), 256>>>(out);
}